// round 11
// baseline (speedup 1.0000x reference)
#include <cuda_runtime.h>
#include <cuda_bf16.h>
#include <cstdint>

#define N 2048
#define D 64
#define JSPLIT 8
#define JCH 256
#define NB 4096
#define HSCALE 4.0f
#define HW 0.25f
#define SRANK 131072

// ---------------- device scratch ----------------
__device__ float g_sq[N];
__device__ float g_isq[N];
__device__ float g_hrn[N];
__device__ float g_srn[N];
__device__ __nv_bfloat16 g_xbf[N*D];     // x row-major bf16
__device__ __nv_bfloat16 g_c1bf[D*N];    // c1 transposed [d][j] bf16
__device__ __nv_bfloat16 g_ybf[D*N];     // y transposed [d][j] bf16
__device__ unsigned g_hist[NB];          // invariant: all-zero at launch entry
__device__ float g_hh;
__device__ __nv_bfloat16 g_pacc1[JSPLIT*N*D];
__device__ __nv_bfloat16 g_pacc2[JSPLIT*N*D];
__device__ float g_prs[JSPLIT*N];
__device__ unsigned g_tick_hist;         // invariant: 0 at launch entry
__device__ unsigned g_tick_main[N/64];   // invariant: 0 at launch entry

// ---------------- helpers ----------------
__device__ __forceinline__ void mma_bf16(float* d, uint32_t a0, uint32_t a1, uint32_t a2,
                                         uint32_t a3, uint32_t b0, uint32_t b1) {
    asm volatile("mma.sync.aligned.m16n8k16.row.col.f32.bf16.bf16.f32 "
        "{%0,%1,%2,%3}, {%4,%5,%6,%7}, {%8,%9}, {%0,%1,%2,%3};"
        : "+f"(d[0]), "+f"(d[1]), "+f"(d[2]), "+f"(d[3])
        : "r"(a0), "r"(a1), "r"(a2), "r"(a3), "r"(b0), "r"(b1));
}
__device__ __forceinline__ void ldmx4(uint32_t* r, uint32_t addr) {
    asm volatile("ldmatrix.sync.aligned.m8n8.x4.shared.b16 {%0,%1,%2,%3}, [%4];"
        : "=r"(r[0]), "=r"(r[1]), "=r"(r[2]), "=r"(r[3]) : "r"(addr));
}
__device__ __forceinline__ uint32_t pack_bf16(float lo, float hi) {
    __nv_bfloat162 h = __floats2bfloat162_rn(lo, hi);
    return *reinterpret_cast<uint32_t*>(&h);
}

// ---------------- combo: prep (blocks 0..255) + sampled hist (256..319) + inline scan ----------------
__global__ __launch_bounds__(256) void k_combo(const float* __restrict__ x,
                                               const float* __restrict__ mu) {
    __shared__ __align__(16) __nv_bfloat16 Abf[64*72];
    __shared__ __align__(16) __nv_bfloat16 Bbf[64*72];
    __shared__ unsigned hist[NB];
    __shared__ float ssqi[64], ssqj[64];
    __shared__ unsigned wsum[9];
    __shared__ float vals[2];
    __shared__ unsigned slast;
    int tid = threadIdx.x;
    int bid = blockIdx.x;

    if (bid < 256) {
        // ---- prep path ----
        int row  = bid * 8 + (tid >> 5);
        int lane = tid & 31;
        const float* xr = x + row * D;
        float x0 = xr[lane], x1 = xr[lane + 32];
        float m0 = mu[lane], m1 = mu[lane + 32];
        float dxx = x0*x0 + x1*x1;
        float dxm = x0*m0 + x1*m1;
        #pragma unroll
        for (int o = 16; o; o >>= 1) {
            dxx += __shfl_xor_sync(0xFFFFFFFFu, dxx, o);
            dxm += __shfl_xor_sync(0xFFFFFFFFu, dxm, o);
        }
        float sq  = dxx;
        float inv = 1.0f / sq;
        float rn  = rsqrtf(sq);
        float coef = -(sq - dxm) * inv;
        float c10 = -(x0 - m0) - x0 * coef - 63.0f * x0 * inv;
        float c11 = -(x1 - m1) - x1 * coef - 63.0f * x1 * inv;
        if (lane == 0) {
            g_sq[row] = sq;
            g_isq[row] = inv;
            g_hrn[row] = 0.5f * rn;
            g_srn[row] = sq * 0.5f * rn;
        }
        g_xbf[row*D + lane]        = __float2bfloat16(x0);
        g_xbf[row*D + lane + 32]   = __float2bfloat16(x1);
        g_c1bf[lane * N + row]        = __float2bfloat16(c10);
        g_c1bf[(lane + 32) * N + row] = __float2bfloat16(c11);
        g_ybf[lane * N + row]         = __float2bfloat16(x0 * rn);
        g_ybf[(lane + 32) * N + row]  = __float2bfloat16(x1 * rn);
        return;
    }
    // ---- sampled pd histogram path: i in [0,256), j in [0,1024) ----
    int pb = bid - 256;
    int i0 = (pb >> 4) * 64, j0 = (pb & 15) * 64;
    {
        int r = tid >> 2, c = (tid & 3) * 16;
        const float* ar = x + (i0 + r) * D + c;
        const float* br = x + (j0 + r) * D + c;
        #pragma unroll
        for (int q = 0; q < 4; q++) {
            float4 va = *(const float4*)(ar + q*4);
            float4 vb = *(const float4*)(br + q*4);
            uint2 ua = {pack_bf16(va.x, va.y), pack_bf16(va.z, va.w)};
            uint2 ub = {pack_bf16(vb.x, vb.y), pack_bf16(vb.z, vb.w)};
            *(uint2*)((char*)Abf + r*144 + (c + q*4)*2) = ua;
            *(uint2*)((char*)Bbf + r*144 + (c + q*4)*2) = ub;
        }
    }
    if (tid < 64) {
        const float4* p = (const float4*)(x + (i0 + tid) * D);
        float s = 0;
        #pragma unroll
        for (int q = 0; q < 16; q++) { float4 v = p[q]; s += v.x*v.x + v.y*v.y + v.z*v.z + v.w*v.w; }
        ssqi[tid] = s;
    } else if (tid < 128) {
        const float4* p = (const float4*)(x + (j0 + tid - 64) * D);
        float s = 0;
        #pragma unroll
        for (int q = 0; q < 16; q++) { float4 v = p[q]; s += v.x*v.x + v.y*v.y + v.z*v.z + v.w*v.w; }
        ssqj[tid - 64] = s;
    }
    for (int i = tid; i < NB; i += 256) hist[i] = 0;
    __syncthreads();
    int wid = tid >> 5, lane = tid & 31;
    int g = lane >> 2, tg = lane & 3;
    int mrow = (wid & 3) * 16;
    int ncol = (wid >> 2) * 32;
    float acc[4][4] = {};
    #pragma unroll
    for (int ks = 0; ks < 4; ks++) {
        int k0 = ks * 16;
        uint32_t ra0 = *(const uint32_t*)((char*)Abf + (mrow+g)*144   + (k0 + 2*tg)*2);
        uint32_t ra1 = *(const uint32_t*)((char*)Abf + (mrow+g+8)*144 + (k0 + 2*tg)*2);
        uint32_t ra2 = *(const uint32_t*)((char*)Abf + (mrow+g)*144   + (k0 + 8 + 2*tg)*2);
        uint32_t ra3 = *(const uint32_t*)((char*)Abf + (mrow+g+8)*144 + (k0 + 8 + 2*tg)*2);
        #pragma unroll
        for (int nt = 0; nt < 4; nt++) {
            uint32_t rb0 = *(const uint32_t*)((char*)Bbf + (ncol+nt*8+g)*144 + (k0 + 2*tg)*2);
            uint32_t rb1 = *(const uint32_t*)((char*)Bbf + (ncol+nt*8+g)*144 + (k0 + 8 + 2*tg)*2);
            mma_bf16(acc[nt], ra0, ra1, ra2, ra3, rb0, rb1);
        }
    }
    float si0 = ssqi[mrow+g], si1 = ssqi[mrow+g+8];
    #pragma unroll
    for (int nt = 0; nt < 4; nt++) {
        int jl = ncol + nt*8 + 2*tg;
        float sj0 = ssqj[jl], sj1 = ssqj[jl+1];
        float v0 = fmaxf(si0 + sj0 - 2.0f*acc[nt][0], 0.0f);
        float v1 = fmaxf(si0 + sj1 - 2.0f*acc[nt][1], 0.0f);
        float v2 = fmaxf(si1 + sj0 - 2.0f*acc[nt][2], 0.0f);
        float v3 = fmaxf(si1 + sj1 - 2.0f*acc[nt][3], 0.0f);
        atomicAdd(&hist[min((unsigned)(v0 * HSCALE), NB - 1u)], 1u);
        atomicAdd(&hist[min((unsigned)(v1 * HSCALE), NB - 1u)], 1u);
        atomicAdd(&hist[min((unsigned)(v2 * HSCALE), NB - 1u)], 1u);
        atomicAdd(&hist[min((unsigned)(v3 * HSCALE), NB - 1u)], 1u);
    }
    __syncthreads();
    for (int i = tid; i < NB; i += 256) {
        unsigned c = hist[i];
        if (c) atomicAdd(&g_hist[i], c);
    }
    // ---- ticket: last of the 64 hist blocks runs the median scan inline ----
    __threadfence();
    if (tid == 0) slast = (atomicAdd(&g_tick_hist, 1u) == 63u) ? 1u : 0u;
    __syncthreads();
    if (!slast) return;
    __threadfence();   // acquire: see all 64 blocks' g_hist contributions

    int t = tid; lane = t & 31; int w = t >> 5;
    unsigned bins[16];
    unsigned s = 0;
    {
        const uint4* p = (const uint4*)&g_hist[t * 16];
        #pragma unroll
        for (int q = 0; q < 4; q++) {
            uint4 u = p[q];
            bins[q*4]=u.x; bins[q*4+1]=u.y; bins[q*4+2]=u.z; bins[q*4+3]=u.w;
            s += u.x + u.y + u.z + u.w;
        }
    }
    unsigned inc = s;
    #pragma unroll
    for (int o = 1; o < 32; o <<= 1) {
        unsigned nv = __shfl_up_sync(0xFFFFFFFFu, inc, o);
        if (lane >= o) inc += nv;
    }
    if (lane == 31) wsum[w] = inc;
    __syncthreads();
    if (t == 0) {
        unsigned c = 0;
        #pragma unroll
        for (int i = 0; i < 8; i++) { unsigned x_ = wsum[i]; wsum[i] = c; c += x_; }
    }
    __syncthreads();
    unsigned base = (inc - s) + wsum[w];
    #pragma unroll
    for (int tau = 0; tau < 2; tau++) {
        unsigned rank = (SRANK - 1u) + (unsigned)tau;
        if (rank >= base && rank < base + s) {
            unsigned cum = base;
            int b = 0;
            while (cum + bins[b] <= rank) { cum += bins[b]; b++; }
            unsigned rem = rank - cum;
            vals[tau] = ((float)(t*16 + b) + ((float)rem + 0.5f) / (float)bins[b]) * HW;
        }
    }
    __syncthreads();
    if (t == 0) {
        float med = 0.5f * (vals[0] + vals[1]);
        g_hh = med * (1.0f / 7.6246189861593985f) + 1e-6f;
        g_tick_hist = 0;                         // restore replay invariant
    }
    {   // re-zero g_hist for next replay
        uint4 z = {0,0,0,0};
        uint4* ph = (uint4*)&g_hist[t * 16];
        ph[0] = z; ph[1] = z; ph[2] = z; ph[3] = z;
    }
}

// ---------------- main: register-fused Gram->exp->dual GEMM + fused finalize ----------------
// CTA: 128 threads, 64 i-rows; JCH=256 (8 j-tiles of 32); grid (32, 8)
__global__ __launch_bounds__(128) void k_main(const float* __restrict__ x,
                                              float* __restrict__ out) {
    __shared__ __align__(16) char XB[2][32*144];
    __shared__ __align__(16) char BCs[2][64*80];
    __shared__ __align__(16) char BYs[2][64*80];
    __shared__ float shs[JCH], sss[JCH], sqj[JCH], sqi[64];
    __shared__ unsigned slast;
    int tid = threadIdx.x, wid = tid >> 5, lane = tid & 31;
    int g = lane >> 2, tg = lane & 3;
    int i0 = blockIdx.x * 64;
    int split = blockIdx.y;
    int jbase = split * JCH;

    shs[tid] = g_hrn[jbase + tid];       shs[tid+128] = g_hrn[jbase + tid + 128];
    sss[tid] = g_srn[jbase + tid];       sss[tid+128] = g_srn[jbase + tid + 128];
    sqj[tid] = g_sq[jbase + tid];        sqj[tid+128] = g_sq[jbase + tid + 128];
    if (tid < 64) sqi[tid] = g_sq[i0 + tid];

    // hoisted x A-fragments
    uint32_t ax[4][4];
    {
        const __nv_bfloat16* r0p = g_xbf + (i0 + wid*16 + g) * D;
        const __nv_bfloat16* r1p = r0p + 8*D;
        #pragma unroll
        for (int ks = 0; ks < 4; ks++) {
            ax[ks][0] = *(const uint32_t*)(r0p + ks*16 + 2*tg);
            ax[ks][1] = *(const uint32_t*)(r1p + ks*16 + 2*tg);
            ax[ks][2] = *(const uint32_t*)(r0p + ks*16 + 8 + 2*tg);
            ax[ks][3] = *(const uint32_t*)(r1p + ks*16 + 8 + 2*tg);
        }
    }
    #pragma unroll
    for (int q = 0; q < 2; q++) {
        int sl = tid*2 + q;
        int r = sl >> 3, c = (sl & 7) * 8;
        *(uint4*)(XB[0] + r*144 + c*2) = *(const uint4*)(g_xbf + (jbase + r) * D + c);
        int r2 = sl >> 2, j8 = (sl & 3) * 8;
        *(uint4*)(BCs[0] + r2*80 + j8*2) = *(const uint4*)(g_c1bf + r2*N + jbase + j8);
        *(uint4*)(BYs[0] + r2*80 + j8*2) = *(const uint4*)(g_ybf  + r2*N + jbase + j8);
    }
    __syncthreads();

    uint32_t uXB = (uint32_t)__cvta_generic_to_shared(XB[0]);
    uint32_t uBC = (uint32_t)__cvta_generic_to_shared(BCs[0]);
    uint32_t uBY = (uint32_t)__cvta_generic_to_shared(BYs[0]);
    float invhh = 1.0f / g_hh;
    float sqi0 = sqi[wid*16 + g], sqi1 = sqi[wid*16 + g + 8];
    float rs0 = 0.0f, rs1 = 0.0f;
    float dacc[2][8][4] = {};

    #pragma unroll 1
    for (int t = 0; t < 8; t++) {
        int buf = t & 1;
        if (t < 7) {
            #pragma unroll
            for (int q = 0; q < 2; q++) {
                int sl = tid*2 + q;
                int r = sl >> 3, c = (sl & 7) * 8;
                *(uint4*)(XB[buf^1] + r*144 + c*2) =
                    *(const uint4*)(g_xbf + (jbase + (t+1)*32 + r) * D + c);
                int r2 = sl >> 2, j8 = (sl & 3) * 8;
                *(uint4*)(BCs[buf^1] + r2*80 + j8*2) =
                    *(const uint4*)(g_c1bf + r2*N + jbase + (t+1)*32 + j8);
                *(uint4*)(BYs[buf^1] + r2*80 + j8*2) =
                    *(const uint4*)(g_ybf  + r2*N + jbase + (t+1)*32 + j8);
            }
        }
        // --- Gram ---
        float ga[4][4] = {};
        {
            uint32_t xb = uXB + buf*4608 + lane*144;
            #pragma unroll
            for (int ks = 0; ks < 4; ks++) {
                uint32_t b0[4], b1[4];
                ldmx4(b0, xb + (ks*16)*2);
                ldmx4(b1, xb + (ks*16 + 8)*2);
                #pragma unroll
                for (int nt = 0; nt < 4; nt++)
                    mma_bf16(ga[nt], ax[ks][0], ax[ks][1], ax[ks][2], ax[ks][3],
                             b0[nt], b1[nt]);
            }
        }
        uint32_t bc = uBC + buf*5120 + lane*80;
        uint32_t by = uBY + buf*5120 + lane*80;
        uint32_t pc0[4], pc1[4], pc2[4], pc3[4];
        uint32_t qc0[4], qc1[4], qc2[4], qc3[4];
        ldmx4(pc0, bc);            ldmx4(qc0, bc + 16);
        ldmx4(pc1, bc + 32*80);    ldmx4(qc1, bc + 32*80 + 16);
        ldmx4(pc2, by);            ldmx4(qc2, by + 16);
        ldmx4(pc3, by + 32*80);    ldmx4(qc3, by + 32*80 + 16);
        // --- epilogue on fragments ---
        uint32_t kf[4][2], mf[4][2];
        #pragma unroll
        for (int nt = 0; nt < 4; nt++) {
            int jl = t*32 + nt*8 + 2*tg;
            float h0 = shs[jl], h1 = shs[jl+1];
            float s0 = sss[jl], s1 = sss[jl+1];
            float q0 = sqj[jl], q1 = sqj[jl+1];
            float v0 = fmaxf(sqi0 + q0 - 2.0f*ga[nt][0], 0.0f);
            float v1 = fmaxf(sqi0 + q1 - 2.0f*ga[nt][1], 0.0f);
            float v2 = fmaxf(sqi1 + q0 - 2.0f*ga[nt][2], 0.0f);
            float v3 = fmaxf(sqi1 + q1 - 2.0f*ga[nt][3], 0.0f);
            float k0 = __expf(-v0*invhh), k1 = __expf(-v1*invhh);
            float k2 = __expf(-v2*invhh), k3 = __expf(-v3*invhh);
            float m0 = k0*(sqi0*h0 + s0 - v0*h0);
            float m1 = k1*(sqi0*h1 + s1 - v1*h1);
            float m2 = k2*(sqi1*h0 + s0 - v2*h0);
            float m3 = k3*(sqi1*h1 + s1 - v3*h1);
            rs0 += k0 + k1; rs1 += k2 + k3;
            kf[nt][0] = pack_bf16(k0, k1); kf[nt][1] = pack_bf16(k2, k3);
            mf[nt][0] = pack_bf16(m0, m1); mf[nt][1] = pack_bf16(m2, m3);
        }
        // --- dual GEMM kstep 0 (preloaded) ---
        {
            uint32_t ka0 = kf[0][0], ka1 = kf[0][1], ka2 = kf[1][0], ka3 = kf[1][1];
            uint32_t ma0 = mf[0][0], ma1 = mf[0][1], ma2 = mf[1][0], ma3 = mf[1][1];
            #pragma unroll
            for (int nt = 0; nt < 4; nt++) {
                mma_bf16(dacc[0][nt],   ka0, ka1, ka2, ka3, pc0[nt], qc0[nt]);
                mma_bf16(dacc[0][nt+4], ka0, ka1, ka2, ka3, pc1[nt], qc1[nt]);
                mma_bf16(dacc[1][nt],   ma0, ma1, ma2, ma3, pc2[nt], qc2[nt]);
                mma_bf16(dacc[1][nt+4], ma0, ma1, ma2, ma3, pc3[nt], qc3[nt]);
            }
        }
        // --- dual GEMM kstep 1 ---
        {
            uint32_t ka0 = kf[2][0], ka1 = kf[2][1], ka2 = kf[3][0], ka3 = kf[3][1];
            uint32_t ma0 = mf[2][0], ma1 = mf[2][1], ma2 = mf[3][0], ma3 = mf[3][1];
            uint32_t b0[4], b1[4];
            ldmx4(b0, bc + 32);
            ldmx4(b1, bc + 48);
            #pragma unroll
            for (int nt = 0; nt < 4; nt++)
                mma_bf16(dacc[0][nt], ka0, ka1, ka2, ka3, b0[nt], b1[nt]);
            ldmx4(b0, bc + 32*80 + 32);
            ldmx4(b1, bc + 32*80 + 48);
            #pragma unroll
            for (int nt = 0; nt < 4; nt++)
                mma_bf16(dacc[0][nt+4], ka0, ka1, ka2, ka3, b0[nt], b1[nt]);
            ldmx4(b0, by + 32);
            ldmx4(b1, by + 48);
            #pragma unroll
            for (int nt = 0; nt < 4; nt++)
                mma_bf16(dacc[1][nt], ma0, ma1, ma2, ma3, b0[nt], b1[nt]);
            ldmx4(b0, by + 32*80 + 32);
            ldmx4(b1, by + 32*80 + 48);
            #pragma unroll
            for (int nt = 0; nt < 4; nt++)
                mma_bf16(dacc[1][nt+4], ma0, ma1, ma2, ma3, b0[nt], b1[nt]);
        }
        __syncthreads();
    }
    // --- write accumulators (bf16 partials) ---
    {
        int row0 = i0 + wid*16 + g;
        __nv_bfloat16* b1 = g_pacc1 + (size_t)split * N * D;
        __nv_bfloat16* b2 = g_pacc2 + (size_t)split * N * D;
        #pragma unroll
        for (int nt = 0; nt < 8; nt++) {
            int co = nt*8 + 2*tg;
            *(uint32_t*)&b1[(size_t)row0 * D + co]     = pack_bf16(dacc[0][nt][0], dacc[0][nt][1]);
            *(uint32_t*)&b1[(size_t)(row0+8) * D + co] = pack_bf16(dacc[0][nt][2], dacc[0][nt][3]);
            *(uint32_t*)&b2[(size_t)row0 * D + co]     = pack_bf16(dacc[1][nt][0], dacc[1][nt][1]);
            *(uint32_t*)&b2[(size_t)(row0+8) * D + co] = pack_bf16(dacc[1][nt][2], dacc[1][nt][3]);
        }
    }
    rs0 += __shfl_xor_sync(0xFFFFFFFFu, rs0, 1);
    rs0 += __shfl_xor_sync(0xFFFFFFFFu, rs0, 2);
    rs1 += __shfl_xor_sync(0xFFFFFFFFu, rs1, 1);
    rs1 += __shfl_xor_sync(0xFFFFFFFFu, rs1, 2);
    if (tg == 0) {
        g_prs[split * N + i0 + wid*16 + g]     = rs0;
        g_prs[split * N + i0 + wid*16 + g + 8] = rs1;
    }
    // --- ticket: last split-CTA of this i-block runs the finalize for its 64 rows ---
    __threadfence();
    if (tid == 0) slast = (atomicAdd(&g_tick_main[blockIdx.x], 1u) == JSPLIT - 1u) ? 1u : 0u;
    __syncthreads();
    if (!slast) return;
    __threadfence();   // acquire: see all splits' pacc/prs
    if (tid == 0) g_tick_main[blockIdx.x] = 0;    // restore replay invariant

    float c2 = 2.0f / g_hh;
    const float sc = 0.1f / 2048.0f;
    for (int rr = wid; rr < 64; rr += 4) {
        int row = i0 + rr;
        float a10 = 0, a11 = 0, a20 = 0, a21 = 0, rstot = 0;
        #pragma unroll
        for (int s = 0; s < JSPLIT; s++) {
            const __nv_bfloat162* p1 = (const __nv_bfloat162*)(g_pacc1 + ((size_t)s * N + row) * D);
            const __nv_bfloat162* p2 = (const __nv_bfloat162*)(g_pacc2 + ((size_t)s * N + row) * D);
            float2 f1 = __bfloat1622float2(p1[lane]);
            float2 f2 = __bfloat1622float2(p2[lane]);
            a10 += f1.x; a11 += f1.y;
            a20 += f2.x; a21 += f2.y;
            rstot += g_prs[s * N + row];
        }
        float x0 = x[row * D + 2*lane], x1 = x[row * D + 2*lane + 1];
        float in0 = a10 + c2 * (rstot * x0 - a20);
        float in1 = a11 + c2 * (rstot * x1 - a21);
        float dot = in0 * x0 + in1 * x1;
        #pragma unroll
        for (int o = 16; o; o >>= 1) dot += __shfl_xor_sync(0xFFFFFFFFu, dot, o);
        float inv = g_isq[row];
        float g0 = in0 - x0 * (dot * inv) - x0 * (63.0f * inv);
        float g1 = in1 - x1 * (dot * inv) - x1 * (63.0f * inv);
        float d0 = fminf(fmaxf(g0 * sc, -1000.0f), 1000.0f);
        float d1 = fminf(fmaxf(g1 * sc, -1000.0f), 1000.0f);
        float2 o2 = {x0 + d0, x1 + d1};
        *(float2*)&out[row * D + 2*lane] = o2;
    }
}

// ---------------- launch ----------------
extern "C" void kernel_launch(void* const* d_in, const int* in_sizes, int n_in,
                              void* d_out, int out_size) {
    const float* x  = (const float*)d_in[0];
    const float* mu = (const float*)d_in[1];
    float* out = (float*)d_out;

    k_combo<<<320, 256>>>(x, mu);
    k_main<<<dim3(N / 64, JSPLIT), 128>>>(x, out);
}

// round 12
// speedup vs baseline: 1.3279x; 1.3279x over previous
#include <cuda_runtime.h>
#include <cuda_bf16.h>
#include <cstdint>

#define N 2048
#define D 64
#define JSPLIT 8
#define JCH 256
#define NB 4096
#define HSCALE 4.0f
#define HW 0.25f
#define SRANK 131072

// ---------------- device scratch ----------------
__device__ float g_sq[N];
__device__ float g_isq[N];
__device__ float g_hrn[N];
__device__ float g_srn[N];
__device__ __nv_bfloat16 g_xbf[N*D];     // x row-major bf16
__device__ __nv_bfloat16 g_c1bf[D*N];    // c1 transposed [d][j] bf16
__device__ __nv_bfloat16 g_ybf[D*N];     // y transposed [d][j] bf16
__device__ unsigned g_hist[NB];          // invariant: all-zero at launch entry
__device__ float g_hh;
__device__ __nv_bfloat16 g_pacc1[JSPLIT*N*D];
__device__ __nv_bfloat16 g_pacc2[JSPLIT*N*D];
__device__ float g_prs[JSPLIT*N];
__device__ unsigned g_tick_hist;         // invariant: 0 at launch entry

// ---------------- helpers ----------------
__device__ __forceinline__ void mma_bf16(float* d, uint32_t a0, uint32_t a1, uint32_t a2,
                                         uint32_t a3, uint32_t b0, uint32_t b1) {
    asm volatile("mma.sync.aligned.m16n8k16.row.col.f32.bf16.bf16.f32 "
        "{%0,%1,%2,%3}, {%4,%5,%6,%7}, {%8,%9}, {%0,%1,%2,%3};"
        : "+f"(d[0]), "+f"(d[1]), "+f"(d[2]), "+f"(d[3])
        : "r"(a0), "r"(a1), "r"(a2), "r"(a3), "r"(b0), "r"(b1));
}
__device__ __forceinline__ void ldmx4(uint32_t* r, uint32_t addr) {
    asm volatile("ldmatrix.sync.aligned.m8n8.x4.shared.b16 {%0,%1,%2,%3}, [%4];"
        : "=r"(r[0]), "=r"(r[1]), "=r"(r[2]), "=r"(r[3]) : "r"(addr));
}
__device__ __forceinline__ uint32_t pack_bf16(float lo, float hi) {
    __nv_bfloat162 h = __floats2bfloat162_rn(lo, hi);
    return *reinterpret_cast<uint32_t*>(&h);
}

// ---------------- combo: prep (blocks 0..255) + sampled hist (256..319) + inline scan ----------------
__global__ __launch_bounds__(256) void k_combo(const float* __restrict__ x,
                                               const float* __restrict__ mu) {
    __shared__ __align__(16) __nv_bfloat16 Abf[64*72];
    __shared__ __align__(16) __nv_bfloat16 Bbf[64*72];
    __shared__ unsigned hist[NB];
    __shared__ float ssqi[64], ssqj[64];
    __shared__ unsigned wsum[9];
    __shared__ float vals[2];
    __shared__ unsigned slast;
    int tid = threadIdx.x;
    int bid = blockIdx.x;

    if (bid < 256) {
        // ---- prep path ----
        int row  = bid * 8 + (tid >> 5);
        int lane = tid & 31;
        const float* xr = x + row * D;
        float x0 = xr[lane], x1 = xr[lane + 32];
        float m0 = mu[lane], m1 = mu[lane + 32];
        float dxx = x0*x0 + x1*x1;
        float dxm = x0*m0 + x1*m1;
        #pragma unroll
        for (int o = 16; o; o >>= 1) {
            dxx += __shfl_xor_sync(0xFFFFFFFFu, dxx, o);
            dxm += __shfl_xor_sync(0xFFFFFFFFu, dxm, o);
        }
        float sq  = dxx;
        float inv = 1.0f / sq;
        float rn  = rsqrtf(sq);
        float coef = -(sq - dxm) * inv;
        float c10 = -(x0 - m0) - x0 * coef - 63.0f * x0 * inv;
        float c11 = -(x1 - m1) - x1 * coef - 63.0f * x1 * inv;
        if (lane == 0) {
            g_sq[row] = sq;
            g_isq[row] = inv;
            g_hrn[row] = 0.5f * rn;
            g_srn[row] = sq * 0.5f * rn;
        }
        g_xbf[row*D + lane]        = __float2bfloat16(x0);
        g_xbf[row*D + lane + 32]   = __float2bfloat16(x1);
        g_c1bf[lane * N + row]        = __float2bfloat16(c10);
        g_c1bf[(lane + 32) * N + row] = __float2bfloat16(c11);
        g_ybf[lane * N + row]         = __float2bfloat16(x0 * rn);
        g_ybf[(lane + 32) * N + row]  = __float2bfloat16(x1 * rn);
        return;
    }
    // ---- sampled pd histogram path: i in [0,256), j in [0,1024) ----
    int pb = bid - 256;
    int i0 = (pb >> 4) * 64, j0 = (pb & 15) * 64;
    {
        int r = tid >> 2, c = (tid & 3) * 16;
        const float* ar = x + (i0 + r) * D + c;
        const float* br = x + (j0 + r) * D + c;
        #pragma unroll
        for (int q = 0; q < 4; q++) {
            float4 va = *(const float4*)(ar + q*4);
            float4 vb = *(const float4*)(br + q*4);
            uint2 ua = {pack_bf16(va.x, va.y), pack_bf16(va.z, va.w)};
            uint2 ub = {pack_bf16(vb.x, vb.y), pack_bf16(vb.z, vb.w)};
            *(uint2*)((char*)Abf + r*144 + (c + q*4)*2) = ua;
            *(uint2*)((char*)Bbf + r*144 + (c + q*4)*2) = ub;
        }
    }
    if (tid < 64) {
        const float4* p = (const float4*)(x + (i0 + tid) * D);
        float s = 0;
        #pragma unroll
        for (int q = 0; q < 16; q++) { float4 v = p[q]; s += v.x*v.x + v.y*v.y + v.z*v.z + v.w*v.w; }
        ssqi[tid] = s;
    } else if (tid < 128) {
        const float4* p = (const float4*)(x + (j0 + tid - 64) * D);
        float s = 0;
        #pragma unroll
        for (int q = 0; q < 16; q++) { float4 v = p[q]; s += v.x*v.x + v.y*v.y + v.z*v.z + v.w*v.w; }
        ssqj[tid - 64] = s;
    }
    for (int i = tid; i < NB; i += 256) hist[i] = 0;
    __syncthreads();
    int wid = tid >> 5, lane = tid & 31;
    int g = lane >> 2, tg = lane & 3;
    int mrow = (wid & 3) * 16;
    int ncol = (wid >> 2) * 32;
    float acc[4][4] = {};
    #pragma unroll
    for (int ks = 0; ks < 4; ks++) {
        int k0 = ks * 16;
        uint32_t ra0 = *(const uint32_t*)((char*)Abf + (mrow+g)*144   + (k0 + 2*tg)*2);
        uint32_t ra1 = *(const uint32_t*)((char*)Abf + (mrow+g+8)*144 + (k0 + 2*tg)*2);
        uint32_t ra2 = *(const uint32_t*)((char*)Abf + (mrow+g)*144   + (k0 + 8 + 2*tg)*2);
        uint32_t ra3 = *(const uint32_t*)((char*)Abf + (mrow+g+8)*144 + (k0 + 8 + 2*tg)*2);
        #pragma unroll
        for (int nt = 0; nt < 4; nt++) {
            uint32_t rb0 = *(const uint32_t*)((char*)Bbf + (ncol+nt*8+g)*144 + (k0 + 2*tg)*2);
            uint32_t rb1 = *(const uint32_t*)((char*)Bbf + (ncol+nt*8+g)*144 + (k0 + 8 + 2*tg)*2);
            mma_bf16(acc[nt], ra0, ra1, ra2, ra3, rb0, rb1);
        }
    }
    float si0 = ssqi[mrow+g], si1 = ssqi[mrow+g+8];
    #pragma unroll
    for (int nt = 0; nt < 4; nt++) {
        int jl = ncol + nt*8 + 2*tg;
        float sj0 = ssqj[jl], sj1 = ssqj[jl+1];
        float v0 = fmaxf(si0 + sj0 - 2.0f*acc[nt][0], 0.0f);
        float v1 = fmaxf(si0 + sj1 - 2.0f*acc[nt][1], 0.0f);
        float v2 = fmaxf(si1 + sj0 - 2.0f*acc[nt][2], 0.0f);
        float v3 = fmaxf(si1 + sj1 - 2.0f*acc[nt][3], 0.0f);
        atomicAdd(&hist[min((unsigned)(v0 * HSCALE), NB - 1u)], 1u);
        atomicAdd(&hist[min((unsigned)(v1 * HSCALE), NB - 1u)], 1u);
        atomicAdd(&hist[min((unsigned)(v2 * HSCALE), NB - 1u)], 1u);
        atomicAdd(&hist[min((unsigned)(v3 * HSCALE), NB - 1u)], 1u);
    }
    __syncthreads();
    for (int i = tid; i < NB; i += 256) {
        unsigned c = hist[i];
        if (c) atomicAdd(&g_hist[i], c);
    }
    // ---- ticket: last of the 64 hist blocks runs the median scan inline ----
    __threadfence();
    if (tid == 0) slast = (atomicAdd(&g_tick_hist, 1u) == 63u) ? 1u : 0u;
    __syncthreads();
    if (!slast) return;
    __threadfence();   // acquire: see all 64 blocks' g_hist contributions

    int t = tid; lane = t & 31; int w = t >> 5;
    unsigned bins[16];
    unsigned s = 0;
    {
        const uint4* p = (const uint4*)&g_hist[t * 16];
        #pragma unroll
        for (int q = 0; q < 4; q++) {
            uint4 u = p[q];
            bins[q*4]=u.x; bins[q*4+1]=u.y; bins[q*4+2]=u.z; bins[q*4+3]=u.w;
            s += u.x + u.y + u.z + u.w;
        }
    }
    unsigned inc = s;
    #pragma unroll
    for (int o = 1; o < 32; o <<= 1) {
        unsigned nv = __shfl_up_sync(0xFFFFFFFFu, inc, o);
        if (lane >= o) inc += nv;
    }
    if (lane == 31) wsum[w] = inc;
    __syncthreads();
    if (t == 0) {
        unsigned c = 0;
        #pragma unroll
        for (int i = 0; i < 8; i++) { unsigned x_ = wsum[i]; wsum[i] = c; c += x_; }
    }
    __syncthreads();
    unsigned base = (inc - s) + wsum[w];
    #pragma unroll
    for (int tau = 0; tau < 2; tau++) {
        unsigned rank = (SRANK - 1u) + (unsigned)tau;
        if (rank >= base && rank < base + s) {
            unsigned cum = base;
            int b = 0;
            while (cum + bins[b] <= rank) { cum += bins[b]; b++; }
            unsigned rem = rank - cum;
            vals[tau] = ((float)(t*16 + b) + ((float)rem + 0.5f) / (float)bins[b]) * HW;
        }
    }
    __syncthreads();
    if (t == 0) {
        float med = 0.5f * (vals[0] + vals[1]);
        g_hh = med * (1.0f / 7.6246189861593985f) + 1e-6f;
        g_tick_hist = 0;                         // restore replay invariant
    }
    {   // re-zero g_hist for next replay
        uint4 z = {0,0,0,0};
        uint4* ph = (uint4*)&g_hist[t * 16];
        ph[0] = z; ph[1] = z; ph[2] = z; ph[3] = z;
    }
}

// ---------------- main: register-fused Gram->exp->dual GEMM (R10 version) ----------------
// CTA: 128 threads, 64 i-rows; JCH=256 (8 j-tiles of 32); grid (32, 8)
__global__ __launch_bounds__(128) void k_main() {
    __shared__ __align__(16) char XB[2][32*144];
    __shared__ __align__(16) char BCs[2][64*80];
    __shared__ __align__(16) char BYs[2][64*80];
    __shared__ float shs[JCH], sss[JCH], sqj[JCH], sqi[64];
    int tid = threadIdx.x, wid = tid >> 5, lane = tid & 31;
    int g = lane >> 2, tg = lane & 3;
    int i0 = blockIdx.x * 64;
    int split = blockIdx.y;
    int jbase = split * JCH;

    shs[tid] = g_hrn[jbase + tid];       shs[tid+128] = g_hrn[jbase + tid + 128];
    sss[tid] = g_srn[jbase + tid];       sss[tid+128] = g_srn[jbase + tid + 128];
    sqj[tid] = g_sq[jbase + tid];        sqj[tid+128] = g_sq[jbase + tid + 128];
    if (tid < 64) sqi[tid] = g_sq[i0 + tid];

    // hoisted x A-fragments
    uint32_t ax[4][4];
    {
        const __nv_bfloat16* r0p = g_xbf + (i0 + wid*16 + g) * D;
        const __nv_bfloat16* r1p = r0p + 8*D;
        #pragma unroll
        for (int ks = 0; ks < 4; ks++) {
            ax[ks][0] = *(const uint32_t*)(r0p + ks*16 + 2*tg);
            ax[ks][1] = *(const uint32_t*)(r1p + ks*16 + 2*tg);
            ax[ks][2] = *(const uint32_t*)(r0p + ks*16 + 8 + 2*tg);
            ax[ks][3] = *(const uint32_t*)(r1p + ks*16 + 8 + 2*tg);
        }
    }
    // fill buf0 with tile 0
    #pragma unroll
    for (int q = 0; q < 2; q++) {
        int sl = tid*2 + q;
        int r = sl >> 3, c = (sl & 7) * 8;
        *(uint4*)(XB[0] + r*144 + c*2) = *(const uint4*)(g_xbf + (jbase + r) * D + c);
        int r2 = sl >> 2, j8 = (sl & 3) * 8;
        *(uint4*)(BCs[0] + r2*80 + j8*2) = *(const uint4*)(g_c1bf + r2*N + jbase + j8);
        *(uint4*)(BYs[0] + r2*80 + j8*2) = *(const uint4*)(g_ybf  + r2*N + jbase + j8);
    }
    __syncthreads();

    uint32_t uXB = (uint32_t)__cvta_generic_to_shared(XB[0]);
    uint32_t uBC = (uint32_t)__cvta_generic_to_shared(BCs[0]);
    uint32_t uBY = (uint32_t)__cvta_generic_to_shared(BYs[0]);
    float invhh = 1.0f / g_hh;
    float sqi0 = sqi[wid*16 + g], sqi1 = sqi[wid*16 + g + 8];
    float rs0 = 0.0f, rs1 = 0.0f;
    float dacc[2][8][4] = {};

    #pragma unroll 1
    for (int t = 0; t < 8; t++) {
        int buf = t & 1;
        if (t < 7) {
            #pragma unroll
            for (int q = 0; q < 2; q++) {
                int sl = tid*2 + q;
                int r = sl >> 3, c = (sl & 7) * 8;
                *(uint4*)(XB[buf^1] + r*144 + c*2) =
                    *(const uint4*)(g_xbf + (jbase + (t+1)*32 + r) * D + c);
                int r2 = sl >> 2, j8 = (sl & 3) * 8;
                *(uint4*)(BCs[buf^1] + r2*80 + j8*2) =
                    *(const uint4*)(g_c1bf + r2*N + jbase + (t+1)*32 + j8);
                *(uint4*)(BYs[buf^1] + r2*80 + j8*2) =
                    *(const uint4*)(g_ybf  + r2*N + jbase + (t+1)*32 + j8);
            }
        }
        // --- Gram ---
        float ga[4][4] = {};
        {
            uint32_t xb = uXB + buf*4608 + lane*144;
            #pragma unroll
            for (int ks = 0; ks < 4; ks++) {
                uint32_t b0[4], b1[4];
                ldmx4(b0, xb + (ks*16)*2);
                ldmx4(b1, xb + (ks*16 + 8)*2);
                #pragma unroll
                for (int nt = 0; nt < 4; nt++)
                    mma_bf16(ga[nt], ax[ks][0], ax[ks][1], ax[ks][2], ax[ks][3],
                             b0[nt], b1[nt]);
            }
        }
        uint32_t bc = uBC + buf*5120 + lane*80;
        uint32_t by = uBY + buf*5120 + lane*80;
        // pre-issue kstep-0 B fragments: LDS overlaps exp epilogue
        uint32_t pc0[4], pc1[4], pc2[4], pc3[4];
        uint32_t qc0[4], qc1[4], qc2[4], qc3[4];
        ldmx4(pc0, bc);            ldmx4(qc0, bc + 16);
        ldmx4(pc1, bc + 32*80);    ldmx4(qc1, bc + 32*80 + 16);
        ldmx4(pc2, by);            ldmx4(qc2, by + 16);
        ldmx4(pc3, by + 32*80);    ldmx4(qc3, by + 32*80 + 16);
        // --- epilogue on fragments ---
        uint32_t kf[4][2], mf[4][2];
        #pragma unroll
        for (int nt = 0; nt < 4; nt++) {
            int jl = t*32 + nt*8 + 2*tg;
            float h0 = shs[jl], h1 = shs[jl+1];
            float s0 = sss[jl], s1 = sss[jl+1];
            float q0 = sqj[jl], q1 = sqj[jl+1];
            float v0 = fmaxf(sqi0 + q0 - 2.0f*ga[nt][0], 0.0f);
            float v1 = fmaxf(sqi0 + q1 - 2.0f*ga[nt][1], 0.0f);
            float v2 = fmaxf(sqi1 + q0 - 2.0f*ga[nt][2], 0.0f);
            float v3 = fmaxf(sqi1 + q1 - 2.0f*ga[nt][3], 0.0f);
            float k0 = __expf(-v0*invhh), k1 = __expf(-v1*invhh);
            float k2 = __expf(-v2*invhh), k3 = __expf(-v3*invhh);
            float m0 = k0*(sqi0*h0 + s0 - v0*h0);
            float m1 = k1*(sqi0*h1 + s1 - v1*h1);
            float m2 = k2*(sqi1*h0 + s0 - v2*h0);
            float m3 = k3*(sqi1*h1 + s1 - v3*h1);
            rs0 += k0 + k1; rs1 += k2 + k3;
            kf[nt][0] = pack_bf16(k0, k1); kf[nt][1] = pack_bf16(k2, k3);
            mf[nt][0] = pack_bf16(m0, m1); mf[nt][1] = pack_bf16(m2, m3);
        }
        // --- dual GEMM kstep 0 (preloaded) ---
        {
            uint32_t ka0 = kf[0][0], ka1 = kf[0][1], ka2 = kf[1][0], ka3 = kf[1][1];
            uint32_t ma0 = mf[0][0], ma1 = mf[0][1], ma2 = mf[1][0], ma3 = mf[1][1];
            #pragma unroll
            for (int nt = 0; nt < 4; nt++) {
                mma_bf16(dacc[0][nt],   ka0, ka1, ka2, ka3, pc0[nt], qc0[nt]);
                mma_bf16(dacc[0][nt+4], ka0, ka1, ka2, ka3, pc1[nt], qc1[nt]);
                mma_bf16(dacc[1][nt],   ma0, ma1, ma2, ma3, pc2[nt], qc2[nt]);
                mma_bf16(dacc[1][nt+4], ma0, ma1, ma2, ma3, pc3[nt], qc3[nt]);
            }
        }
        // --- dual GEMM kstep 1 ---
        {
            uint32_t ka0 = kf[2][0], ka1 = kf[2][1], ka2 = kf[3][0], ka3 = kf[3][1];
            uint32_t ma0 = mf[2][0], ma1 = mf[2][1], ma2 = mf[3][0], ma3 = mf[3][1];
            uint32_t b0[4], b1[4];
            ldmx4(b0, bc + 32);
            ldmx4(b1, bc + 48);
            #pragma unroll
            for (int nt = 0; nt < 4; nt++)
                mma_bf16(dacc[0][nt], ka0, ka1, ka2, ka3, b0[nt], b1[nt]);
            ldmx4(b0, bc + 32*80 + 32);
            ldmx4(b1, bc + 32*80 + 48);
            #pragma unroll
            for (int nt = 0; nt < 4; nt++)
                mma_bf16(dacc[0][nt+4], ka0, ka1, ka2, ka3, b0[nt], b1[nt]);
            ldmx4(b0, by + 32);
            ldmx4(b1, by + 48);
            #pragma unroll
            for (int nt = 0; nt < 4; nt++)
                mma_bf16(dacc[1][nt], ma0, ma1, ma2, ma3, b0[nt], b1[nt]);
            ldmx4(b0, by + 32*80 + 32);
            ldmx4(b1, by + 32*80 + 48);
            #pragma unroll
            for (int nt = 0; nt < 4; nt++)
                mma_bf16(dacc[1][nt+4], ma0, ma1, ma2, ma3, b0[nt], b1[nt]);
        }
        __syncthreads();
    }
    // --- write accumulators (bf16 partials) ---
    {
        int row0 = i0 + wid*16 + g;
        __nv_bfloat16* b1 = g_pacc1 + (size_t)split * N * D;
        __nv_bfloat16* b2 = g_pacc2 + (size_t)split * N * D;
        #pragma unroll
        for (int nt = 0; nt < 8; nt++) {
            int co = nt*8 + 2*tg;
            *(uint32_t*)&b1[(size_t)row0 * D + co]     = pack_bf16(dacc[0][nt][0], dacc[0][nt][1]);
            *(uint32_t*)&b1[(size_t)(row0+8) * D + co] = pack_bf16(dacc[0][nt][2], dacc[0][nt][3]);
            *(uint32_t*)&b2[(size_t)row0 * D + co]     = pack_bf16(dacc[1][nt][0], dacc[1][nt][1]);
            *(uint32_t*)&b2[(size_t)(row0+8) * D + co] = pack_bf16(dacc[1][nt][2], dacc[1][nt][3]);
        }
    }
    rs0 += __shfl_xor_sync(0xFFFFFFFFu, rs0, 1);
    rs0 += __shfl_xor_sync(0xFFFFFFFFu, rs0, 2);
    rs1 += __shfl_xor_sync(0xFFFFFFFFu, rs1, 1);
    rs1 += __shfl_xor_sync(0xFFFFFFFFu, rs1, 2);
    if (tg == 0) {
        g_prs[split * N + i0 + wid*16 + g]     = rs0;
        g_prs[split * N + i0 + wid*16 + g + 8] = rs1;
    }
}

// ---------------- finalize: split-reduce (bf16 partials) + projection + update ----------------
__global__ void k_fin(const float* __restrict__ x, float* __restrict__ out) {
    int row  = blockIdx.x * 8 + (threadIdx.x >> 5);
    int lane = threadIdx.x & 31;
    float a10 = 0, a11 = 0, a20 = 0, a21 = 0, rstot = 0;
    #pragma unroll
    for (int s = 0; s < JSPLIT; s++) {
        const __nv_bfloat162* p1 = (const __nv_bfloat162*)(g_pacc1 + ((size_t)s * N + row) * D);
        const __nv_bfloat162* p2 = (const __nv_bfloat162*)(g_pacc2 + ((size_t)s * N + row) * D);
        float2 f1 = __bfloat1622float2(p1[lane]);
        float2 f2 = __bfloat1622float2(p2[lane]);
        a10 += f1.x; a11 += f1.y;
        a20 += f2.x; a21 += f2.y;
        rstot += g_prs[s * N + row];
    }
    float c2 = 2.0f / g_hh;
    float x0 = x[row * D + 2*lane], x1 = x[row * D + 2*lane + 1];
    float in0 = a10 + c2 * (rstot * x0 - a20);
    float in1 = a11 + c2 * (rstot * x1 - a21);
    float dot = in0 * x0 + in1 * x1;
    #pragma unroll
    for (int o = 16; o; o >>= 1) dot += __shfl_xor_sync(0xFFFFFFFFu, dot, o);
    float inv = g_isq[row];
    float g0 = in0 - x0 * (dot * inv) - x0 * (63.0f * inv);
    float g1 = in1 - x1 * (dot * inv) - x1 * (63.0f * inv);
    const float sc = 0.1f / 2048.0f;
    float d0 = fminf(fmaxf(g0 * sc, -1000.0f), 1000.0f);
    float d1 = fminf(fmaxf(g1 * sc, -1000.0f), 1000.0f);
    float2 o2 = {x0 + d0, x1 + d1};
    *(float2*)&out[row * D + 2*lane] = o2;
}

// ---------------- launch ----------------
extern "C" void kernel_launch(void* const* d_in, const int* in_sizes, int n_in,
                              void* d_out, int out_size) {
    const float* x  = (const float*)d_in[0];
    const float* mu = (const float*)d_in[1];
    float* out = (float*)d_out;

    k_combo<<<320, 256>>>(x, mu);
    k_main<<<dim3(N / 64, JSPLIT), 128>>>();
    k_fin<<<N / 8, 256>>>(x, out);
}

// round 13
// speedup vs baseline: 1.4087x; 1.0609x over previous
#include <cuda_runtime.h>
#include <cuda_bf16.h>
#include <cstdint>

#define N 2048
#define D 64
#define JSPLIT 8
#define JCH 256
#define NB 4096
#define HSCALE 4.0f
#define HW 0.25f
#define NHB 16                 // hist blocks: 128 rows x 512 cols sample
#define SRANK 32768            // 128*512/2

// ---------------- device scratch ----------------
__device__ float g_sq[N];
__device__ float g_isq[N];
__device__ float g_hrn[N];
__device__ float g_srn[N];
__device__ __nv_bfloat16 g_xbf[N*D];     // x row-major bf16
__device__ __nv_bfloat16 g_c1bf[D*N];    // c1 transposed [d][j] bf16
__device__ __nv_bfloat16 g_ybf[D*N];     // y transposed [d][j] bf16
__device__ unsigned g_hist[NB];          // invariant: all-zero at launch entry
__device__ float g_hh;
__device__ __nv_bfloat16 g_pacc1[JSPLIT*N*D];
__device__ __nv_bfloat16 g_pacc2[JSPLIT*N*D];
__device__ float g_prs[JSPLIT*N];
__device__ unsigned g_tick_hist;         // invariant: 0 at launch entry

// ---------------- helpers ----------------
__device__ __forceinline__ void mma_bf16(float* d, uint32_t a0, uint32_t a1, uint32_t a2,
                                         uint32_t a3, uint32_t b0, uint32_t b1) {
    asm volatile("mma.sync.aligned.m16n8k16.row.col.f32.bf16.bf16.f32 "
        "{%0,%1,%2,%3}, {%4,%5,%6,%7}, {%8,%9}, {%0,%1,%2,%3};"
        : "+f"(d[0]), "+f"(d[1]), "+f"(d[2]), "+f"(d[3])
        : "r"(a0), "r"(a1), "r"(a2), "r"(a3), "r"(b0), "r"(b1));
}
__device__ __forceinline__ void ldmx4(uint32_t* r, uint32_t addr) {
    asm volatile("ldmatrix.sync.aligned.m8n8.x4.shared.b16 {%0,%1,%2,%3}, [%4];"
        : "=r"(r[0]), "=r"(r[1]), "=r"(r[2]), "=r"(r[3]) : "r"(addr));
}
__device__ __forceinline__ uint32_t pack_bf16(float lo, float hi) {
    __nv_bfloat162 h = __floats2bfloat162_rn(lo, hi);
    return *reinterpret_cast<uint32_t*>(&h);
}

// ---------------- combo: prep (blocks 0..255) + sampled hist (256..271) + inline scan ----------------
__global__ __launch_bounds__(256) void k_combo(const float* __restrict__ x,
                                               const float* __restrict__ mu) {
    __shared__ __align__(16) __nv_bfloat16 Abf[64*72];
    __shared__ __align__(16) __nv_bfloat16 Bbf[64*72];
    __shared__ unsigned hist[NB];
    __shared__ float ssqi[64], ssqj[64];
    __shared__ unsigned wsum[9];
    __shared__ float vals[2];
    __shared__ unsigned slast;
    int tid = threadIdx.x;
    int bid = blockIdx.x;

    if (bid < 256) {
        // ---- prep path ----
        __shared__ __align__(16) __nv_bfloat16 sc1[64][8];
        __shared__ __align__(16) __nv_bfloat16 sy[64][8];
        int r8   = tid >> 5;            // row within 8-row group
        int lane = tid & 31;
        int row  = bid * 8 + r8;
        const float* xr = x + row * D;
        float x0 = xr[lane], x1 = xr[lane + 32];
        float m0 = mu[lane], m1 = mu[lane + 32];
        float dxx = x0*x0 + x1*x1;
        float dxm = x0*m0 + x1*m1;
        #pragma unroll
        for (int o = 16; o; o >>= 1) {
            dxx += __shfl_xor_sync(0xFFFFFFFFu, dxx, o);
            dxm += __shfl_xor_sync(0xFFFFFFFFu, dxm, o);
        }
        float sq  = dxx;
        float inv = 1.0f / sq;
        float rn  = rsqrtf(sq);
        float coef = -(sq - dxm) * inv;
        float c10 = -(x0 - m0) - x0 * coef - 63.0f * x0 * inv;
        float c11 = -(x1 - m1) - x1 * coef - 63.0f * x1 * inv;
        if (lane == 0) {
            g_sq[row] = sq;
            g_isq[row] = inv;
            g_hrn[row] = 0.5f * rn;
            g_srn[row] = sq * 0.5f * rn;
        }
        g_xbf[row*D + lane]      = __float2bfloat16(x0);
        g_xbf[row*D + lane + 32] = __float2bfloat16(x1);
        // stage transposed tiles in smem, then write coalesced 16B chunks
        sc1[lane][r8]      = __float2bfloat16(c10);
        sc1[lane + 32][r8] = __float2bfloat16(c11);
        sy[lane][r8]       = __float2bfloat16(x0 * rn);
        sy[lane + 32][r8]  = __float2bfloat16(x1 * rn);
        __syncthreads();
        int j0 = bid * 8;
        if (tid < 64) {
            *(uint4*)&g_c1bf[tid * N + j0] = *(const uint4*)&sc1[tid][0];
        } else if (tid < 128) {
            int d = tid - 64;
            *(uint4*)&g_ybf[d * N + j0] = *(const uint4*)&sy[d][0];
        }
        return;
    }
    // ---- sampled pd histogram: i in [0,128), j in [0,512); 16 blocks ----
    int pb = bid - 256;
    int i0 = (pb >> 3) * 64, j0 = (pb & 7) * 64;
    {
        int r = tid >> 2, c = (tid & 3) * 16;
        const float* ar = x + (i0 + r) * D + c;
        const float* br = x + (j0 + r) * D + c;
        #pragma unroll
        for (int q = 0; q < 4; q++) {
            float4 va = *(const float4*)(ar + q*4);
            float4 vb = *(const float4*)(br + q*4);
            uint2 ua = {pack_bf16(va.x, va.y), pack_bf16(va.z, va.w)};
            uint2 ub = {pack_bf16(vb.x, vb.y), pack_bf16(vb.z, vb.w)};
            *(uint2*)((char*)Abf + r*144 + (c + q*4)*2) = ua;
            *(uint2*)((char*)Bbf + r*144 + (c + q*4)*2) = ub;
        }
    }
    if (tid < 64) {
        const float4* p = (const float4*)(x + (i0 + tid) * D);
        float s = 0;
        #pragma unroll
        for (int q = 0; q < 16; q++) { float4 v = p[q]; s += v.x*v.x + v.y*v.y + v.z*v.z + v.w*v.w; }
        ssqi[tid] = s;
    } else if (tid < 128) {
        const float4* p = (const float4*)(x + (j0 + tid - 64) * D);
        float s = 0;
        #pragma unroll
        for (int q = 0; q < 16; q++) { float4 v = p[q]; s += v.x*v.x + v.y*v.y + v.z*v.z + v.w*v.w; }
        ssqj[tid - 64] = s;
    }
    for (int i = tid; i < NB; i += 256) hist[i] = 0;
    __syncthreads();
    int wid = tid >> 5, lane = tid & 31;
    int g = lane >> 2, tg = lane & 3;
    int mrow = (wid & 3) * 16;
    int ncol = (wid >> 2) * 32;
    float acc[4][4] = {};
    #pragma unroll
    for (int ks = 0; ks < 4; ks++) {
        int k0 = ks * 16;
        uint32_t ra0 = *(const uint32_t*)((char*)Abf + (mrow+g)*144   + (k0 + 2*tg)*2);
        uint32_t ra1 = *(const uint32_t*)((char*)Abf + (mrow+g+8)*144 + (k0 + 2*tg)*2);
        uint32_t ra2 = *(const uint32_t*)((char*)Abf + (mrow+g)*144   + (k0 + 8 + 2*tg)*2);
        uint32_t ra3 = *(const uint32_t*)((char*)Abf + (mrow+g+8)*144 + (k0 + 8 + 2*tg)*2);
        #pragma unroll
        for (int nt = 0; nt < 4; nt++) {
            uint32_t rb0 = *(const uint32_t*)((char*)Bbf + (ncol+nt*8+g)*144 + (k0 + 2*tg)*2);
            uint32_t rb1 = *(const uint32_t*)((char*)Bbf + (ncol+nt*8+g)*144 + (k0 + 8 + 2*tg)*2);
            mma_bf16(acc[nt], ra0, ra1, ra2, ra3, rb0, rb1);
        }
    }
    float si0 = ssqi[mrow+g], si1 = ssqi[mrow+g+8];
    #pragma unroll
    for (int nt = 0; nt < 4; nt++) {
        int jl = ncol + nt*8 + 2*tg;
        float sj0 = ssqj[jl], sj1 = ssqj[jl+1];
        float v0 = fmaxf(si0 + sj0 - 2.0f*acc[nt][0], 0.0f);
        float v1 = fmaxf(si0 + sj1 - 2.0f*acc[nt][1], 0.0f);
        float v2 = fmaxf(si1 + sj0 - 2.0f*acc[nt][2], 0.0f);
        float v3 = fmaxf(si1 + sj1 - 2.0f*acc[nt][3], 0.0f);
        atomicAdd(&hist[min((unsigned)(v0 * HSCALE), NB - 1u)], 1u);
        atomicAdd(&hist[min((unsigned)(v1 * HSCALE), NB - 1u)], 1u);
        atomicAdd(&hist[min((unsigned)(v2 * HSCALE), NB - 1u)], 1u);
        atomicAdd(&hist[min((unsigned)(v3 * HSCALE), NB - 1u)], 1u);
    }
    __syncthreads();
    for (int i = tid; i < NB; i += 256) {
        unsigned c = hist[i];
        if (c) atomicAdd(&g_hist[i], c);
    }
    // ---- ticket: last hist block runs the median scan inline ----
    __threadfence();
    if (tid == 0) slast = (atomicAdd(&g_tick_hist, 1u) == NHB - 1u) ? 1u : 0u;
    __syncthreads();
    if (!slast) return;
    __threadfence();   // acquire

    int t = tid; lane = t & 31; int w = t >> 5;
    unsigned bins[16];
    unsigned s = 0;
    {
        const uint4* p = (const uint4*)&g_hist[t * 16];
        #pragma unroll
        for (int q = 0; q < 4; q++) {
            uint4 u = p[q];
            bins[q*4]=u.x; bins[q*4+1]=u.y; bins[q*4+2]=u.z; bins[q*4+3]=u.w;
            s += u.x + u.y + u.z + u.w;
        }
    }
    unsigned inc = s;
    #pragma unroll
    for (int o = 1; o < 32; o <<= 1) {
        unsigned nv = __shfl_up_sync(0xFFFFFFFFu, inc, o);
        if (lane >= o) inc += nv;
    }
    if (lane == 31) wsum[w] = inc;
    __syncthreads();
    if (t == 0) {
        unsigned c = 0;
        #pragma unroll
        for (int i = 0; i < 8; i++) { unsigned x_ = wsum[i]; wsum[i] = c; c += x_; }
    }
    __syncthreads();
    unsigned base = (inc - s) + wsum[w];
    #pragma unroll
    for (int tau = 0; tau < 2; tau++) {
        unsigned rank = (SRANK - 1u) + (unsigned)tau;
        if (rank >= base && rank < base + s) {
            unsigned cum = base;
            int b = 0;
            while (cum + bins[b] <= rank) { cum += bins[b]; b++; }
            unsigned rem = rank - cum;
            vals[tau] = ((float)(t*16 + b) + ((float)rem + 0.5f) / (float)bins[b]) * HW;
        }
    }
    __syncthreads();
    if (t == 0) {
        float med = 0.5f * (vals[0] + vals[1]);
        g_hh = med * (1.0f / 7.6246189861593985f) + 1e-6f;
        g_tick_hist = 0;                         // restore replay invariant
    }
    {   // re-zero g_hist for next replay
        uint4 z = {0,0,0,0};
        uint4* ph = (uint4*)&g_hist[t * 16];
        ph[0] = z; ph[1] = z; ph[2] = z; ph[3] = z;
    }
}

// ---------------- main: register-fused Gram->exp->dual GEMM ----------------
// CTA: 128 threads, 64 i-rows; JCH=256 (8 j-tiles of 32); grid (32, 8)
__global__ __launch_bounds__(128) void k_main() {
    __shared__ __align__(16) char XB[2][32*144];
    __shared__ __align__(16) char BCs[2][64*80];
    __shared__ __align__(16) char BYs[2][64*80];
    __shared__ float shs[JCH], sss[JCH], sqj[JCH], sqi[64];
    int tid = threadIdx.x, wid = tid >> 5, lane = tid & 31;
    int g = lane >> 2, tg = lane & 3;
    int i0 = blockIdx.x * 64;
    int split = blockIdx.y;
    int jbase = split * JCH;

    shs[tid] = g_hrn[jbase + tid];       shs[tid+128] = g_hrn[jbase + tid + 128];
    sss[tid] = g_srn[jbase + tid];       sss[tid+128] = g_srn[jbase + tid + 128];
    sqj[tid] = g_sq[jbase + tid];        sqj[tid+128] = g_sq[jbase + tid + 128];
    if (tid < 64) sqi[tid] = g_sq[i0 + tid];

    uint32_t ax[4][4];
    {
        const __nv_bfloat16* r0p = g_xbf + (i0 + wid*16 + g) * D;
        const __nv_bfloat16* r1p = r0p + 8*D;
        #pragma unroll
        for (int ks = 0; ks < 4; ks++) {
            ax[ks][0] = *(const uint32_t*)(r0p + ks*16 + 2*tg);
            ax[ks][1] = *(const uint32_t*)(r1p + ks*16 + 2*tg);
            ax[ks][2] = *(const uint32_t*)(r0p + ks*16 + 8 + 2*tg);
            ax[ks][3] = *(const uint32_t*)(r1p + ks*16 + 8 + 2*tg);
        }
    }
    #pragma unroll
    for (int q = 0; q < 2; q++) {
        int sl = tid*2 + q;
        int r = sl >> 3, c = (sl & 7) * 8;
        *(uint4*)(XB[0] + r*144 + c*2) = *(const uint4*)(g_xbf + (jbase + r) * D + c);
        int r2 = sl >> 2, j8 = (sl & 3) * 8;
        *(uint4*)(BCs[0] + r2*80 + j8*2) = *(const uint4*)(g_c1bf + r2*N + jbase + j8);
        *(uint4*)(BYs[0] + r2*80 + j8*2) = *(const uint4*)(g_ybf  + r2*N + jbase + j8);
    }
    __syncthreads();

    uint32_t uXB = (uint32_t)__cvta_generic_to_shared(XB[0]);
    uint32_t uBC = (uint32_t)__cvta_generic_to_shared(BCs[0]);
    uint32_t uBY = (uint32_t)__cvta_generic_to_shared(BYs[0]);
    float invhh = 1.0f / g_hh;
    float sqi0 = sqi[wid*16 + g], sqi1 = sqi[wid*16 + g + 8];
    float rs0 = 0.0f, rs1 = 0.0f;
    float dacc[2][8][4] = {};

    #pragma unroll 1
    for (int t = 0; t < 8; t++) {
        int buf = t & 1;
        if (t < 7) {
            #pragma unroll
            for (int q = 0; q < 2; q++) {
                int sl = tid*2 + q;
                int r = sl >> 3, c = (sl & 7) * 8;
                *(uint4*)(XB[buf^1] + r*144 + c*2) =
                    *(const uint4*)(g_xbf + (jbase + (t+1)*32 + r) * D + c);
                int r2 = sl >> 2, j8 = (sl & 3) * 8;
                *(uint4*)(BCs[buf^1] + r2*80 + j8*2) =
                    *(const uint4*)(g_c1bf + r2*N + jbase + (t+1)*32 + j8);
                *(uint4*)(BYs[buf^1] + r2*80 + j8*2) =
                    *(const uint4*)(g_ybf  + r2*N + jbase + (t+1)*32 + j8);
            }
        }
        float ga[4][4] = {};
        {
            uint32_t xb = uXB + buf*4608 + lane*144;
            #pragma unroll
            for (int ks = 0; ks < 4; ks++) {
                uint32_t b0[4], b1[4];
                ldmx4(b0, xb + (ks*16)*2);
                ldmx4(b1, xb + (ks*16 + 8)*2);
                #pragma unroll
                for (int nt = 0; nt < 4; nt++)
                    mma_bf16(ga[nt], ax[ks][0], ax[ks][1], ax[ks][2], ax[ks][3],
                             b0[nt], b1[nt]);
            }
        }
        uint32_t bc = uBC + buf*5120 + lane*80;
        uint32_t by = uBY + buf*5120 + lane*80;
        uint32_t pc0[4], pc1[4], pc2[4], pc3[4];
        uint32_t qc0[4], qc1[4], qc2[4], qc3[4];
        ldmx4(pc0, bc);            ldmx4(qc0, bc + 16);
        ldmx4(pc1, bc + 32*80);    ldmx4(qc1, bc + 32*80 + 16);
        ldmx4(pc2, by);            ldmx4(qc2, by + 16);
        ldmx4(pc3, by + 32*80);    ldmx4(qc3, by + 32*80 + 16);
        uint32_t kf[4][2], mf[4][2];
        #pragma unroll
        for (int nt = 0; nt < 4; nt++) {
            int jl = t*32 + nt*8 + 2*tg;
            float h0 = shs[jl], h1 = shs[jl+1];
            float s0 = sss[jl], s1 = sss[jl+1];
            float q0 = sqj[jl], q1 = sqj[jl+1];
            float v0 = fmaxf(sqi0 + q0 - 2.0f*ga[nt][0], 0.0f);
            float v1 = fmaxf(sqi0 + q1 - 2.0f*ga[nt][1], 0.0f);
            float v2 = fmaxf(sqi1 + q0 - 2.0f*ga[nt][2], 0.0f);
            float v3 = fmaxf(sqi1 + q1 - 2.0f*ga[nt][3], 0.0f);
            float k0 = __expf(-v0*invhh), k1 = __expf(-v1*invhh);
            float k2 = __expf(-v2*invhh), k3 = __expf(-v3*invhh);
            float m0 = k0*(sqi0*h0 + s0 - v0*h0);
            float m1 = k1*(sqi0*h1 + s1 - v1*h1);
            float m2 = k2*(sqi1*h0 + s0 - v2*h0);
            float m3 = k3*(sqi1*h1 + s1 - v3*h1);
            rs0 += k0 + k1; rs1 += k2 + k3;
            kf[nt][0] = pack_bf16(k0, k1); kf[nt][1] = pack_bf16(k2, k3);
            mf[nt][0] = pack_bf16(m0, m1); mf[nt][1] = pack_bf16(m2, m3);
        }
        {
            uint32_t ka0 = kf[0][0], ka1 = kf[0][1], ka2 = kf[1][0], ka3 = kf[1][1];
            uint32_t ma0 = mf[0][0], ma1 = mf[0][1], ma2 = mf[1][0], ma3 = mf[1][1];
            #pragma unroll
            for (int nt = 0; nt < 4; nt++) {
                mma_bf16(dacc[0][nt],   ka0, ka1, ka2, ka3, pc0[nt], qc0[nt]);
                mma_bf16(dacc[0][nt+4], ka0, ka1, ka2, ka3, pc1[nt], qc1[nt]);
                mma_bf16(dacc[1][nt],   ma0, ma1, ma2, ma3, pc2[nt], qc2[nt]);
                mma_bf16(dacc[1][nt+4], ma0, ma1, ma2, ma3, pc3[nt], qc3[nt]);
            }
        }
        {
            uint32_t ka0 = kf[2][0], ka1 = kf[2][1], ka2 = kf[3][0], ka3 = kf[3][1];
            uint32_t ma0 = mf[2][0], ma1 = mf[2][1], ma2 = mf[3][0], ma3 = mf[3][1];
            uint32_t b0[4], b1[4];
            ldmx4(b0, bc + 32);
            ldmx4(b1, bc + 48);
            #pragma unroll
            for (int nt = 0; nt < 4; nt++)
                mma_bf16(dacc[0][nt], ka0, ka1, ka2, ka3, b0[nt], b1[nt]);
            ldmx4(b0, bc + 32*80 + 32);
            ldmx4(b1, bc + 32*80 + 48);
            #pragma unroll
            for (int nt = 0; nt < 4; nt++)
                mma_bf16(dacc[0][nt+4], ka0, ka1, ka2, ka3, b0[nt], b1[nt]);
            ldmx4(b0, by + 32);
            ldmx4(b1, by + 48);
            #pragma unroll
            for (int nt = 0; nt < 4; nt++)
                mma_bf16(dacc[1][nt], ma0, ma1, ma2, ma3, b0[nt], b1[nt]);
            ldmx4(b0, by + 32*80 + 32);
            ldmx4(b1, by + 32*80 + 48);
            #pragma unroll
            for (int nt = 0; nt < 4; nt++)
                mma_bf16(dacc[1][nt+4], ma0, ma1, ma2, ma3, b0[nt], b1[nt]);
        }
        __syncthreads();
    }
    {
        int row0 = i0 + wid*16 + g;
        __nv_bfloat16* b1 = g_pacc1 + (size_t)split * N * D;
        __nv_bfloat16* b2 = g_pacc2 + (size_t)split * N * D;
        #pragma unroll
        for (int nt = 0; nt < 8; nt++) {
            int co = nt*8 + 2*tg;
            *(uint32_t*)&b1[(size_t)row0 * D + co]     = pack_bf16(dacc[0][nt][0], dacc[0][nt][1]);
            *(uint32_t*)&b1[(size_t)(row0+8) * D + co] = pack_bf16(dacc[0][nt][2], dacc[0][nt][3]);
            *(uint32_t*)&b2[(size_t)row0 * D + co]     = pack_bf16(dacc[1][nt][0], dacc[1][nt][1]);
            *(uint32_t*)&b2[(size_t)(row0+8) * D + co] = pack_bf16(dacc[1][nt][2], dacc[1][nt][3]);
        }
    }
    rs0 += __shfl_xor_sync(0xFFFFFFFFu, rs0, 1);
    rs0 += __shfl_xor_sync(0xFFFFFFFFu, rs0, 2);
    rs1 += __shfl_xor_sync(0xFFFFFFFFu, rs1, 1);
    rs1 += __shfl_xor_sync(0xFFFFFFFFu, rs1, 2);
    if (tg == 0) {
        g_prs[split * N + i0 + wid*16 + g]     = rs0;
        g_prs[split * N + i0 + wid*16 + g + 8] = rs1;
    }
}

// ---------------- finalize ----------------
__global__ void k_fin(const float* __restrict__ x, float* __restrict__ out) {
    int row  = blockIdx.x * 8 + (threadIdx.x >> 5);
    int lane = threadIdx.x & 31;
    float a10 = 0, a11 = 0, a20 = 0, a21 = 0, rstot = 0;
    #pragma unroll
    for (int s = 0; s < JSPLIT; s++) {
        const __nv_bfloat162* p1 = (const __nv_bfloat162*)(g_pacc1 + ((size_t)s * N + row) * D);
        const __nv_bfloat162* p2 = (const __nv_bfloat162*)(g_pacc2 + ((size_t)s * N + row) * D);
        float2 f1 = __bfloat1622float2(p1[lane]);
        float2 f2 = __bfloat1622float2(p2[lane]);
        a10 += f1.x; a11 += f1.y;
        a20 += f2.x; a21 += f2.y;
        rstot += g_prs[s * N + row];
    }
    float c2 = 2.0f / g_hh;
    float x0 = x[row * D + 2*lane], x1 = x[row * D + 2*lane + 1];
    float in0 = a10 + c2 * (rstot * x0 - a20);
    float in1 = a11 + c2 * (rstot * x1 - a21);
    float dot = in0 * x0 + in1 * x1;
    #pragma unroll
    for (int o = 16; o; o >>= 1) dot += __shfl_xor_sync(0xFFFFFFFFu, dot, o);
    float inv = g_isq[row];
    float g0 = in0 - x0 * (dot * inv) - x0 * (63.0f * inv);
    float g1 = in1 - x1 * (dot * inv) - x1 * (63.0f * inv);
    const float sc = 0.1f / 2048.0f;
    float d0 = fminf(fmaxf(g0 * sc, -1000.0f), 1000.0f);
    float d1 = fminf(fmaxf(g1 * sc, -1000.0f), 1000.0f);
    float2 o2 = {x0 + d0, x1 + d1};
    *(float2*)&out[row * D + 2*lane] = o2;
}

// ---------------- launch ----------------
extern "C" void kernel_launch(void* const* d_in, const int* in_sizes, int n_in,
                              void* d_out, int out_size) {
    const float* x  = (const float*)d_in[0];
    const float* mu = (const float*)d_in[1];
    float* out = (float*)d_out;

    k_combo<<<256 + NHB, 256>>>(x, mu);
    k_main<<<dim3(N / 64, JSPLIT), 128>>>();
    k_fin<<<N / 8, 256>>>(x, out);
}

// round 14
// speedup vs baseline: 1.5265x; 1.0836x over previous
#include <cuda_runtime.h>
#include <cuda_bf16.h>
#include <cstdint>

#define N 2048
#define D 64
#define JSPLIT 8
#define JCH 256
#define NB 4096
#define HSCALE 4.0f
#define HW 0.25f
#define SRANK 2048             // 4096-sample median

// ---------------- device scratch ----------------
__device__ float g_sq[N];
__device__ float g_isq[N];
__device__ float g_hrn[N];
__device__ float g_srn[N];
__device__ __nv_bfloat16 g_xbf[N*D];     // x row-major bf16
__device__ __nv_bfloat16 g_c1bf[D*N];    // c1 transposed [d][j] bf16
__device__ __nv_bfloat16 g_ybf[D*N];     // y transposed [d][j] bf16
__device__ float g_hh;
__device__ __nv_bfloat16 g_pacc1[JSPLIT*N*D];
__device__ __nv_bfloat16 g_pacc2[JSPLIT*N*D];
__device__ float g_prs[JSPLIT*N];

// ---------------- helpers ----------------
__device__ __forceinline__ void mma_bf16(float* d, uint32_t a0, uint32_t a1, uint32_t a2,
                                         uint32_t a3, uint32_t b0, uint32_t b1) {
    asm volatile("mma.sync.aligned.m16n8k16.row.col.f32.bf16.bf16.f32 "
        "{%0,%1,%2,%3}, {%4,%5,%6,%7}, {%8,%9}, {%0,%1,%2,%3};"
        : "+f"(d[0]), "+f"(d[1]), "+f"(d[2]), "+f"(d[3])
        : "r"(a0), "r"(a1), "r"(a2), "r"(a3), "r"(b0), "r"(b1));
}
__device__ __forceinline__ void ldmx4(uint32_t* r, uint32_t addr) {
    asm volatile("ldmatrix.sync.aligned.m8n8.x4.shared.b16 {%0,%1,%2,%3}, [%4];"
        : "=r"(r[0]), "=r"(r[1]), "=r"(r[2]), "=r"(r[3]) : "r"(addr));
}
__device__ __forceinline__ uint32_t pack_bf16(float lo, float hi) {
    __nv_bfloat162 h = __floats2bfloat162_rn(lo, hi);
    return *reinterpret_cast<uint32_t*>(&h);
}

// ---------------- combo: prep (blocks 0..255) + single-block sampled median (block 256) ----------------
__global__ __launch_bounds__(256) void k_combo(const float* __restrict__ x,
                                               const float* __restrict__ mu) {
    __shared__ __align__(16) __nv_bfloat16 Abf[64*72];
    __shared__ __align__(16) __nv_bfloat16 Bbf[64*72];
    __shared__ unsigned hist[NB];
    __shared__ float ssqi[64], ssqj[64];
    __shared__ unsigned wsum[9];
    __shared__ float vals[2];
    int tid = threadIdx.x;
    int bid = blockIdx.x;

    if (bid < 256) {
        // ---- prep path ----
        __shared__ __align__(16) __nv_bfloat16 sc1[64][8];
        __shared__ __align__(16) __nv_bfloat16 sy[64][8];
        int r8   = tid >> 5;
        int lane = tid & 31;
        int row  = bid * 8 + r8;
        const float* xr = x + row * D;
        float x0 = xr[lane], x1 = xr[lane + 32];
        float m0 = mu[lane], m1 = mu[lane + 32];
        float dxx = x0*x0 + x1*x1;
        float dxm = x0*m0 + x1*m1;
        #pragma unroll
        for (int o = 16; o; o >>= 1) {
            dxx += __shfl_xor_sync(0xFFFFFFFFu, dxx, o);
            dxm += __shfl_xor_sync(0xFFFFFFFFu, dxm, o);
        }
        float sq  = dxx;
        float inv = 1.0f / sq;
        float rn  = rsqrtf(sq);
        float coef = -(sq - dxm) * inv;
        float c10 = -(x0 - m0) - x0 * coef - 63.0f * x0 * inv;
        float c11 = -(x1 - m1) - x1 * coef - 63.0f * x1 * inv;
        if (lane == 0) {
            g_sq[row] = sq;
            g_isq[row] = inv;
            g_hrn[row] = 0.5f * rn;
            g_srn[row] = sq * 0.5f * rn;
        }
        g_xbf[row*D + lane]      = __float2bfloat16(x0);
        g_xbf[row*D + lane + 32] = __float2bfloat16(x1);
        sc1[lane][r8]      = __float2bfloat16(c10);
        sc1[lane + 32][r8] = __float2bfloat16(c11);
        sy[lane][r8]       = __float2bfloat16(x0 * rn);
        sy[lane + 32][r8]  = __float2bfloat16(x1 * rn);
        __syncthreads();
        int j0 = bid * 8;
        if (tid < 64) {
            *(uint4*)&g_c1bf[tid * N + j0] = *(const uint4*)&sc1[tid][0];
        } else if (tid < 128) {
            int d = tid - 64;
            *(uint4*)&g_ybf[d * N + j0] = *(const uint4*)&sy[d][0];
        }
        return;
    }
    // ---- single-block sampled median: i in [0,64), j in [64,128) ----
    {
        int r = tid >> 2, c = (tid & 3) * 16;
        const float* ar = x + r * D + c;
        const float* br = x + (64 + r) * D + c;
        #pragma unroll
        for (int q = 0; q < 4; q++) {
            float4 va = *(const float4*)(ar + q*4);
            float4 vb = *(const float4*)(br + q*4);
            uint2 ua = {pack_bf16(va.x, va.y), pack_bf16(va.z, va.w)};
            uint2 ub = {pack_bf16(vb.x, vb.y), pack_bf16(vb.z, vb.w)};
            *(uint2*)((char*)Abf + r*144 + (c + q*4)*2) = ua;
            *(uint2*)((char*)Bbf + r*144 + (c + q*4)*2) = ub;
        }
    }
    if (tid < 64) {
        const float4* p = (const float4*)(x + tid * D);
        float s = 0;
        #pragma unroll
        for (int q = 0; q < 16; q++) { float4 v = p[q]; s += v.x*v.x + v.y*v.y + v.z*v.z + v.w*v.w; }
        ssqi[tid] = s;
    } else if (tid < 128) {
        const float4* p = (const float4*)(x + tid * D);   // rows 64..127
        float s = 0;
        #pragma unroll
        for (int q = 0; q < 16; q++) { float4 v = p[q]; s += v.x*v.x + v.y*v.y + v.z*v.z + v.w*v.w; }
        ssqj[tid - 64] = s;
    }
    for (int i = tid; i < NB; i += 256) hist[i] = 0;
    __syncthreads();
    int wid = tid >> 5, lane = tid & 31;
    int g = lane >> 2, tg = lane & 3;
    int mrow = (wid & 3) * 16;
    int ncol = (wid >> 2) * 32;
    float acc[4][4] = {};
    #pragma unroll
    for (int ks = 0; ks < 4; ks++) {
        int k0 = ks * 16;
        uint32_t ra0 = *(const uint32_t*)((char*)Abf + (mrow+g)*144   + (k0 + 2*tg)*2);
        uint32_t ra1 = *(const uint32_t*)((char*)Abf + (mrow+g+8)*144 + (k0 + 2*tg)*2);
        uint32_t ra2 = *(const uint32_t*)((char*)Abf + (mrow+g)*144   + (k0 + 8 + 2*tg)*2);
        uint32_t ra3 = *(const uint32_t*)((char*)Abf + (mrow+g+8)*144 + (k0 + 8 + 2*tg)*2);
        #pragma unroll
        for (int nt = 0; nt < 4; nt++) {
            uint32_t rb0 = *(const uint32_t*)((char*)Bbf + (ncol+nt*8+g)*144 + (k0 + 2*tg)*2);
            uint32_t rb1 = *(const uint32_t*)((char*)Bbf + (ncol+nt*8+g)*144 + (k0 + 8 + 2*tg)*2);
            mma_bf16(acc[nt], ra0, ra1, ra2, ra3, rb0, rb1);
        }
    }
    float si0 = ssqi[mrow+g], si1 = ssqi[mrow+g+8];
    #pragma unroll
    for (int nt = 0; nt < 4; nt++) {
        int jl = ncol + nt*8 + 2*tg;
        float sj0 = ssqj[jl], sj1 = ssqj[jl+1];
        float v0 = fmaxf(si0 + sj0 - 2.0f*acc[nt][0], 0.0f);
        float v1 = fmaxf(si0 + sj1 - 2.0f*acc[nt][1], 0.0f);
        float v2 = fmaxf(si1 + sj0 - 2.0f*acc[nt][2], 0.0f);
        float v3 = fmaxf(si1 + sj1 - 2.0f*acc[nt][3], 0.0f);
        atomicAdd(&hist[min((unsigned)(v0 * HSCALE), NB - 1u)], 1u);
        atomicAdd(&hist[min((unsigned)(v1 * HSCALE), NB - 1u)], 1u);
        atomicAdd(&hist[min((unsigned)(v2 * HSCALE), NB - 1u)], 1u);
        atomicAdd(&hist[min((unsigned)(v3 * HSCALE), NB - 1u)], 1u);
    }
    __syncthreads();
    // ---- in-block scan: find the two middle samples, interpolate, write g_hh ----
    int t = tid; int w = t >> 5;
    unsigned bins[16];
    unsigned s = 0;
    #pragma unroll
    for (int q = 0; q < 16; q++) { bins[q] = hist[t*16 + q]; s += bins[q]; }
    unsigned inc = s;
    #pragma unroll
    for (int o = 1; o < 32; o <<= 1) {
        unsigned nv = __shfl_up_sync(0xFFFFFFFFu, inc, o);
        if (lane >= o) inc += nv;
    }
    if (lane == 31) wsum[w] = inc;
    __syncthreads();
    if (t == 0) {
        unsigned c = 0;
        #pragma unroll
        for (int i = 0; i < 8; i++) { unsigned x_ = wsum[i]; wsum[i] = c; c += x_; }
    }
    __syncthreads();
    unsigned base = (inc - s) + wsum[w];
    #pragma unroll
    for (int tau = 0; tau < 2; tau++) {
        unsigned rank = (SRANK - 1u) + (unsigned)tau;
        if (rank >= base && rank < base + s) {
            unsigned cum = base;
            int b = 0;
            while (cum + bins[b] <= rank) { cum += bins[b]; b++; }
            unsigned rem = rank - cum;
            vals[tau] = ((float)(t*16 + b) + ((float)rem + 0.5f) / (float)bins[b]) * HW;
        }
    }
    __syncthreads();
    if (t == 0) {
        float med = 0.5f * (vals[0] + vals[1]);
        g_hh = med * (1.0f / 7.6246189861593985f) + 1e-6f;   // median/ln(2048)+1e-6
    }
}

// ---------------- main: register-fused Gram->exp->dual GEMM ----------------
// CTA: 128 threads, 64 i-rows; JCH=256 (8 j-tiles of 32); grid (32, 8)
__global__ __launch_bounds__(128) void k_main() {
    __shared__ __align__(16) char XB[2][32*144];
    __shared__ __align__(16) char BCs[2][64*80];
    __shared__ __align__(16) char BYs[2][64*80];
    __shared__ float shs[JCH], sss[JCH], sqj[JCH], sqi[64];
    int tid = threadIdx.x, wid = tid >> 5, lane = tid & 31;
    int g = lane >> 2, tg = lane & 3;
    int i0 = blockIdx.x * 64;
    int split = blockIdx.y;
    int jbase = split * JCH;

    shs[tid] = g_hrn[jbase + tid];       shs[tid+128] = g_hrn[jbase + tid + 128];
    sss[tid] = g_srn[jbase + tid];       sss[tid+128] = g_srn[jbase + tid + 128];
    sqj[tid] = g_sq[jbase + tid];        sqj[tid+128] = g_sq[jbase + tid + 128];
    if (tid < 64) sqi[tid] = g_sq[i0 + tid];

    uint32_t ax[4][4];
    {
        const __nv_bfloat16* r0p = g_xbf + (i0 + wid*16 + g) * D;
        const __nv_bfloat16* r1p = r0p + 8*D;
        #pragma unroll
        for (int ks = 0; ks < 4; ks++) {
            ax[ks][0] = *(const uint32_t*)(r0p + ks*16 + 2*tg);
            ax[ks][1] = *(const uint32_t*)(r1p + ks*16 + 2*tg);
            ax[ks][2] = *(const uint32_t*)(r0p + ks*16 + 8 + 2*tg);
            ax[ks][3] = *(const uint32_t*)(r1p + ks*16 + 8 + 2*tg);
        }
    }
    #pragma unroll
    for (int q = 0; q < 2; q++) {
        int sl = tid*2 + q;
        int r = sl >> 3, c = (sl & 7) * 8;
        *(uint4*)(XB[0] + r*144 + c*2) = *(const uint4*)(g_xbf + (jbase + r) * D + c);
        int r2 = sl >> 2, j8 = (sl & 3) * 8;
        *(uint4*)(BCs[0] + r2*80 + j8*2) = *(const uint4*)(g_c1bf + r2*N + jbase + j8);
        *(uint4*)(BYs[0] + r2*80 + j8*2) = *(const uint4*)(g_ybf  + r2*N + jbase + j8);
    }
    __syncthreads();

    uint32_t uXB = (uint32_t)__cvta_generic_to_shared(XB[0]);
    uint32_t uBC = (uint32_t)__cvta_generic_to_shared(BCs[0]);
    uint32_t uBY = (uint32_t)__cvta_generic_to_shared(BYs[0]);
    float invhh = 1.0f / g_hh;
    float sqi0 = sqi[wid*16 + g], sqi1 = sqi[wid*16 + g + 8];
    float rs0 = 0.0f, rs1 = 0.0f;
    float dacc[2][8][4] = {};

    #pragma unroll 1
    for (int t = 0; t < 8; t++) {
        int buf = t & 1;
        if (t < 7) {
            #pragma unroll
            for (int q = 0; q < 2; q++) {
                int sl = tid*2 + q;
                int r = sl >> 3, c = (sl & 7) * 8;
                *(uint4*)(XB[buf^1] + r*144 + c*2) =
                    *(const uint4*)(g_xbf + (jbase + (t+1)*32 + r) * D + c);
                int r2 = sl >> 2, j8 = (sl & 3) * 8;
                *(uint4*)(BCs[buf^1] + r2*80 + j8*2) =
                    *(const uint4*)(g_c1bf + r2*N + jbase + (t+1)*32 + j8);
                *(uint4*)(BYs[buf^1] + r2*80 + j8*2) =
                    *(const uint4*)(g_ybf  + r2*N + jbase + (t+1)*32 + j8);
            }
        }
        float ga[4][4] = {};
        {
            uint32_t xb = uXB + buf*4608 + lane*144;
            #pragma unroll
            for (int ks = 0; ks < 4; ks++) {
                uint32_t b0[4], b1[4];
                ldmx4(b0, xb + (ks*16)*2);
                ldmx4(b1, xb + (ks*16 + 8)*2);
                #pragma unroll
                for (int nt = 0; nt < 4; nt++)
                    mma_bf16(ga[nt], ax[ks][0], ax[ks][1], ax[ks][2], ax[ks][3],
                             b0[nt], b1[nt]);
            }
        }
        uint32_t bc = uBC + buf*5120 + lane*80;
        uint32_t by = uBY + buf*5120 + lane*80;
        uint32_t pc0[4], pc1[4], pc2[4], pc3[4];
        uint32_t qc0[4], qc1[4], qc2[4], qc3[4];
        ldmx4(pc0, bc);            ldmx4(qc0, bc + 16);
        ldmx4(pc1, bc + 32*80);    ldmx4(qc1, bc + 32*80 + 16);
        ldmx4(pc2, by);            ldmx4(qc2, by + 16);
        ldmx4(pc3, by + 32*80);    ldmx4(qc3, by + 32*80 + 16);
        uint32_t kf[4][2], mf[4][2];
        #pragma unroll
        for (int nt = 0; nt < 4; nt++) {
            int jl = t*32 + nt*8 + 2*tg;
            float h0 = shs[jl], h1 = shs[jl+1];
            float s0 = sss[jl], s1 = sss[jl+1];
            float q0 = sqj[jl], q1 = sqj[jl+1];
            float v0 = fmaxf(sqi0 + q0 - 2.0f*ga[nt][0], 0.0f);
            float v1 = fmaxf(sqi0 + q1 - 2.0f*ga[nt][1], 0.0f);
            float v2 = fmaxf(sqi1 + q0 - 2.0f*ga[nt][2], 0.0f);
            float v3 = fmaxf(sqi1 + q1 - 2.0f*ga[nt][3], 0.0f);
            float k0 = __expf(-v0*invhh), k1 = __expf(-v1*invhh);
            float k2 = __expf(-v2*invhh), k3 = __expf(-v3*invhh);
            float m0 = k0*(sqi0*h0 + s0 - v0*h0);
            float m1 = k1*(sqi0*h1 + s1 - v1*h1);
            float m2 = k2*(sqi1*h0 + s0 - v2*h0);
            float m3 = k3*(sqi1*h1 + s1 - v3*h1);
            rs0 += k0 + k1; rs1 += k2 + k3;
            kf[nt][0] = pack_bf16(k0, k1); kf[nt][1] = pack_bf16(k2, k3);
            mf[nt][0] = pack_bf16(m0, m1); mf[nt][1] = pack_bf16(m2, m3);
        }
        {
            uint32_t ka0 = kf[0][0], ka1 = kf[0][1], ka2 = kf[1][0], ka3 = kf[1][1];
            uint32_t ma0 = mf[0][0], ma1 = mf[0][1], ma2 = mf[1][0], ma3 = mf[1][1];
            #pragma unroll
            for (int nt = 0; nt < 4; nt++) {
                mma_bf16(dacc[0][nt],   ka0, ka1, ka2, ka3, pc0[nt], qc0[nt]);
                mma_bf16(dacc[0][nt+4], ka0, ka1, ka2, ka3, pc1[nt], qc1[nt]);
                mma_bf16(dacc[1][nt],   ma0, ma1, ma2, ma3, pc2[nt], qc2[nt]);
                mma_bf16(dacc[1][nt+4], ma0, ma1, ma2, ma3, pc3[nt], qc3[nt]);
            }
        }
        {
            uint32_t ka0 = kf[2][0], ka1 = kf[2][1], ka2 = kf[3][0], ka3 = kf[3][1];
            uint32_t ma0 = mf[2][0], ma1 = mf[2][1], ma2 = mf[3][0], ma3 = mf[3][1];
            uint32_t b0[4], b1[4];
            ldmx4(b0, bc + 32);
            ldmx4(b1, bc + 48);
            #pragma unroll
            for (int nt = 0; nt < 4; nt++)
                mma_bf16(dacc[0][nt], ka0, ka1, ka2, ka3, b0[nt], b1[nt]);
            ldmx4(b0, bc + 32*80 + 32);
            ldmx4(b1, bc + 32*80 + 48);
            #pragma unroll
            for (int nt = 0; nt < 4; nt++)
                mma_bf16(dacc[0][nt+4], ka0, ka1, ka2, ka3, b0[nt], b1[nt]);
            ldmx4(b0, by + 32);
            ldmx4(b1, by + 48);
            #pragma unroll
            for (int nt = 0; nt < 4; nt++)
                mma_bf16(dacc[1][nt], ma0, ma1, ma2, ma3, b0[nt], b1[nt]);
            ldmx4(b0, by + 32*80 + 32);
            ldmx4(b1, by + 32*80 + 48);
            #pragma unroll
            for (int nt = 0; nt < 4; nt++)
                mma_bf16(dacc[1][nt+4], ma0, ma1, ma2, ma3, b0[nt], b1[nt]);
        }
        __syncthreads();
    }
    {
        int row0 = i0 + wid*16 + g;
        __nv_bfloat16* b1 = g_pacc1 + (size_t)split * N * D;
        __nv_bfloat16* b2 = g_pacc2 + (size_t)split * N * D;
        #pragma unroll
        for (int nt = 0; nt < 8; nt++) {
            int co = nt*8 + 2*tg;
            *(uint32_t*)&b1[(size_t)row0 * D + co]     = pack_bf16(dacc[0][nt][0], dacc[0][nt][1]);
            *(uint32_t*)&b1[(size_t)(row0+8) * D + co] = pack_bf16(dacc[0][nt][2], dacc[0][nt][3]);
            *(uint32_t*)&b2[(size_t)row0 * D + co]     = pack_bf16(dacc[1][nt][0], dacc[1][nt][1]);
            *(uint32_t*)&b2[(size_t)(row0+8) * D + co] = pack_bf16(dacc[1][nt][2], dacc[1][nt][3]);
        }
    }
    rs0 += __shfl_xor_sync(0xFFFFFFFFu, rs0, 1);
    rs0 += __shfl_xor_sync(0xFFFFFFFFu, rs0, 2);
    rs1 += __shfl_xor_sync(0xFFFFFFFFu, rs1, 1);
    rs1 += __shfl_xor_sync(0xFFFFFFFFu, rs1, 2);
    if (tg == 0) {
        g_prs[split * N + i0 + wid*16 + g]     = rs0;
        g_prs[split * N + i0 + wid*16 + g + 8] = rs1;
    }
}

// ---------------- finalize ----------------
__global__ void k_fin(const float* __restrict__ x, float* __restrict__ out) {
    int row  = blockIdx.x * 8 + (threadIdx.x >> 5);
    int lane = threadIdx.x & 31;
    float a10 = 0, a11 = 0, a20 = 0, a21 = 0, rstot = 0;
    #pragma unroll
    for (int s = 0; s < JSPLIT; s++) {
        const __nv_bfloat162* p1 = (const __nv_bfloat162*)(g_pacc1 + ((size_t)s * N + row) * D);
        const __nv_bfloat162* p2 = (const __nv_bfloat162*)(g_pacc2 + ((size_t)s * N + row) * D);
        float2 f1 = __bfloat1622float2(p1[lane]);
        float2 f2 = __bfloat1622float2(p2[lane]);
        a10 += f1.x; a11 += f1.y;
        a20 += f2.x; a21 += f2.y;
        rstot += g_prs[s * N + row];
    }
    float c2 = 2.0f / g_hh;
    float x0 = x[row * D + 2*lane], x1 = x[row * D + 2*lane + 1];
    float in0 = a10 + c2 * (rstot * x0 - a20);
    float in1 = a11 + c2 * (rstot * x1 - a21);
    float dot = in0 * x0 + in1 * x1;
    #pragma unroll
    for (int o = 16; o; o >>= 1) dot += __shfl_xor_sync(0xFFFFFFFFu, dot, o);
    float inv = g_isq[row];
    float g0 = in0 - x0 * (dot * inv) - x0 * (63.0f * inv);
    float g1 = in1 - x1 * (dot * inv) - x1 * (63.0f * inv);
    const float sc = 0.1f / 2048.0f;
    float d0 = fminf(fmaxf(g0 * sc, -1000.0f), 1000.0f);
    float d1 = fminf(fmaxf(g1 * sc, -1000.0f), 1000.0f);
    float2 o2 = {x0 + d0, x1 + d1};
    *(float2*)&out[row * D + 2*lane] = o2;
}

// ---------------- launch ----------------
extern "C" void kernel_launch(void* const* d_in, const int* in_sizes, int n_in,
                              void* d_out, int out_size) {
    const float* x  = (const float*)d_in[0];
    const float* mu = (const float*)d_in[1];
    float* out = (float*)d_out;

    k_combo<<<257, 256>>>(x, mu);
    k_main<<<dim3(N / 64, JSPLIT), 128>>>();
    k_fin<<<N / 8, 256>>>(x, out);
}

// round 15
// speedup vs baseline: 1.6552x; 1.0843x over previous
#include <cuda_runtime.h>
#include <cuda_bf16.h>
#include <cstdint>

#define N 2048
#define D 64
#define JSPLIT 8
#define JCH 256
#define NB 1024
#define HSCALE 1.0f
#define HW 1.0f
#define SRANK 2048             // 4096-sample median

// ---------------- device scratch ----------------
__device__ float g_sq[N];
__device__ float g_isq[N];
__device__ float g_hrn[N];
__device__ float g_srn[N];
__device__ __nv_bfloat16 g_xbf[N*D];     // x row-major bf16
__device__ __nv_bfloat16 g_c1bf[D*N];    // c1 transposed [d][j] bf16
__device__ __nv_bfloat16 g_ybf[D*N];     // y transposed [d][j] bf16
__device__ float g_hh;
__device__ __nv_bfloat16 g_pacc1[JSPLIT*N*D];
__device__ __nv_bfloat16 g_pacc2[JSPLIT*N*D];
__device__ float g_prs[JSPLIT*N];

// ---------------- helpers ----------------
__device__ __forceinline__ void mma_bf16(float* d, uint32_t a0, uint32_t a1, uint32_t a2,
                                         uint32_t a3, uint32_t b0, uint32_t b1) {
    asm volatile("mma.sync.aligned.m16n8k16.row.col.f32.bf16.bf16.f32 "
        "{%0,%1,%2,%3}, {%4,%5,%6,%7}, {%8,%9}, {%0,%1,%2,%3};"
        : "+f"(d[0]), "+f"(d[1]), "+f"(d[2]), "+f"(d[3])
        : "r"(a0), "r"(a1), "r"(a2), "r"(a3), "r"(b0), "r"(b1));
}
__device__ __forceinline__ void ldmx4(uint32_t* r, uint32_t addr) {
    asm volatile("ldmatrix.sync.aligned.m8n8.x4.shared.b16 {%0,%1,%2,%3}, [%4];"
        : "=r"(r[0]), "=r"(r[1]), "=r"(r[2]), "=r"(r[3]) : "r"(addr));
}
__device__ __forceinline__ uint32_t pack_bf16(float lo, float hi) {
    __nv_bfloat162 h = __floats2bfloat162_rn(lo, hi);
    return *reinterpret_cast<uint32_t*>(&h);
}

// ---------------- combo: prep (blocks 0..255) + single-block sampled median (block 256) ----------------
__global__ __launch_bounds__(256) void k_combo(const float* __restrict__ x,
                                               const float* __restrict__ mu) {
    __shared__ __align__(16) __nv_bfloat16 Abf[64*72];
    __shared__ __align__(16) __nv_bfloat16 Bbf[64*72];
    __shared__ unsigned hist[NB];
    __shared__ float ssq[128];
    __shared__ unsigned wsum[9];
    __shared__ float vals[2];
    int tid = threadIdx.x;
    int bid = blockIdx.x;

    if (bid < 256) {
        // ---- prep path ----
        __shared__ __align__(16) __nv_bfloat16 sc1[64][8];
        __shared__ __align__(16) __nv_bfloat16 sy[64][8];
        int r8   = tid >> 5;
        int lane = tid & 31;
        int row  = bid * 8 + r8;
        const float* xr = x + row * D;
        float x0 = xr[lane], x1 = xr[lane + 32];
        float m0 = mu[lane], m1 = mu[lane + 32];
        float dxx = x0*x0 + x1*x1;
        float dxm = x0*m0 + x1*m1;
        #pragma unroll
        for (int o = 16; o; o >>= 1) {
            dxx += __shfl_xor_sync(0xFFFFFFFFu, dxx, o);
            dxm += __shfl_xor_sync(0xFFFFFFFFu, dxm, o);
        }
        float sq  = dxx;
        float inv = 1.0f / sq;
        float rn  = rsqrtf(sq);
        float coef = -(sq - dxm) * inv;
        float c10 = -(x0 - m0) - x0 * coef - 63.0f * x0 * inv;
        float c11 = -(x1 - m1) - x1 * coef - 63.0f * x1 * inv;
        if (lane == 0) {
            g_sq[row] = sq;
            g_isq[row] = inv;
            g_hrn[row] = 0.5f * rn;
            g_srn[row] = sq * 0.5f * rn;
        }
        g_xbf[row*D + lane]      = __float2bfloat16(x0);
        g_xbf[row*D + lane + 32] = __float2bfloat16(x1);
        sc1[lane][r8]      = __float2bfloat16(c10);
        sc1[lane + 32][r8] = __float2bfloat16(c11);
        sy[lane][r8]       = __float2bfloat16(x0 * rn);
        sy[lane + 32][r8]  = __float2bfloat16(x1 * rn);
        __syncthreads();
        int j0 = bid * 8;
        if (tid < 64) {
            *(uint4*)&g_c1bf[tid * N + j0] = *(const uint4*)&sc1[tid][0];
        } else if (tid < 128) {
            int d = tid - 64;
            *(uint4*)&g_ybf[d * N + j0] = *(const uint4*)&sy[d][0];
        }
        return;
    }
    // ---- single-block sampled median: i in [0,64), j in [64,128) ----
    // norms of rows 0..127: 2 threads per row, 8 float4 loads each, pair-combine
    {
        int row = tid >> 1, half = tid & 1;
        const float4* p = (const float4*)(x + row * D + half * 32);
        float s = 0;
        #pragma unroll
        for (int q = 0; q < 8; q++) { float4 v = p[q]; s += v.x*v.x + v.y*v.y + v.z*v.z + v.w*v.w; }
        s += __shfl_xor_sync(0xFFFFFFFFu, s, 1);
        if (half == 0) ssq[row] = s;
    }
    {
        int r = tid >> 2, c = (tid & 3) * 16;
        const float* ar = x + r * D + c;
        const float* br = x + (64 + r) * D + c;
        #pragma unroll
        for (int q = 0; q < 4; q++) {
            float4 va = *(const float4*)(ar + q*4);
            float4 vb = *(const float4*)(br + q*4);
            uint2 ua = {pack_bf16(va.x, va.y), pack_bf16(va.z, va.w)};
            uint2 ub = {pack_bf16(vb.x, vb.y), pack_bf16(vb.z, vb.w)};
            *(uint2*)((char*)Abf + r*144 + (c + q*4)*2) = ua;
            *(uint2*)((char*)Bbf + r*144 + (c + q*4)*2) = ub;
        }
    }
    #pragma unroll
    for (int q = 0; q < NB/256; q++) hist[tid + q*256] = 0;
    __syncthreads();
    int wid = tid >> 5, lane = tid & 31;
    int g = lane >> 2, tg = lane & 3;
    int mrow = (wid & 3) * 16;
    int ncol = (wid >> 2) * 32;
    float acc[4][4] = {};
    #pragma unroll
    for (int ks = 0; ks < 4; ks++) {
        int k0 = ks * 16;
        uint32_t ra0 = *(const uint32_t*)((char*)Abf + (mrow+g)*144   + (k0 + 2*tg)*2);
        uint32_t ra1 = *(const uint32_t*)((char*)Abf + (mrow+g+8)*144 + (k0 + 2*tg)*2);
        uint32_t ra2 = *(const uint32_t*)((char*)Abf + (mrow+g)*144   + (k0 + 8 + 2*tg)*2);
        uint32_t ra3 = *(const uint32_t*)((char*)Abf + (mrow+g+8)*144 + (k0 + 8 + 2*tg)*2);
        #pragma unroll
        for (int nt = 0; nt < 4; nt++) {
            uint32_t rb0 = *(const uint32_t*)((char*)Bbf + (ncol+nt*8+g)*144 + (k0 + 2*tg)*2);
            uint32_t rb1 = *(const uint32_t*)((char*)Bbf + (ncol+nt*8+g)*144 + (k0 + 8 + 2*tg)*2);
            mma_bf16(acc[nt], ra0, ra1, ra2, ra3, rb0, rb1);
        }
    }
    float si0 = ssq[mrow+g], si1 = ssq[mrow+g+8];
    #pragma unroll
    for (int nt = 0; nt < 4; nt++) {
        int jl = ncol + nt*8 + 2*tg;
        float sj0 = ssq[64 + jl], sj1 = ssq[64 + jl + 1];
        float v0 = fmaxf(si0 + sj0 - 2.0f*acc[nt][0], 0.0f);
        float v1 = fmaxf(si0 + sj1 - 2.0f*acc[nt][1], 0.0f);
        float v2 = fmaxf(si1 + sj0 - 2.0f*acc[nt][2], 0.0f);
        float v3 = fmaxf(si1 + sj1 - 2.0f*acc[nt][3], 0.0f);
        atomicAdd(&hist[min((unsigned)(v0 * HSCALE), NB - 1u)], 1u);
        atomicAdd(&hist[min((unsigned)(v1 * HSCALE), NB - 1u)], 1u);
        atomicAdd(&hist[min((unsigned)(v2 * HSCALE), NB - 1u)], 1u);
        atomicAdd(&hist[min((unsigned)(v3 * HSCALE), NB - 1u)], 1u);
    }
    __syncthreads();
    // ---- in-block scan: find the two middle samples, interpolate, write g_hh ----
    int t = tid; int w = t >> 5;
    unsigned bins[4];
    unsigned s = 0;
    #pragma unroll
    for (int q = 0; q < 4; q++) { bins[q] = hist[t*4 + q]; s += bins[q]; }
    unsigned inc = s;
    #pragma unroll
    for (int o = 1; o < 32; o <<= 1) {
        unsigned nv = __shfl_up_sync(0xFFFFFFFFu, inc, o);
        if (lane >= o) inc += nv;
    }
    if (lane == 31) wsum[w] = inc;
    __syncthreads();
    if (t == 0) {
        unsigned c = 0;
        #pragma unroll
        for (int i = 0; i < 8; i++) { unsigned x_ = wsum[i]; wsum[i] = c; c += x_; }
    }
    __syncthreads();
    unsigned base = (inc - s) + wsum[w];
    #pragma unroll
    for (int tau = 0; tau < 2; tau++) {
        unsigned rank = (SRANK - 1u) + (unsigned)tau;
        if (rank >= base && rank < base + s) {
            unsigned cum = base;
            int b = 0;
            while (cum + bins[b] <= rank) { cum += bins[b]; b++; }
            unsigned rem = rank - cum;
            vals[tau] = ((float)(t*4 + b) + ((float)rem + 0.5f) / (float)bins[b]) * HW;
        }
    }
    __syncthreads();
    if (t == 0) {
        float med = 0.5f * (vals[0] + vals[1]);
        g_hh = med * (1.0f / 7.6246189861593985f) + 1e-6f;   // median/ln(2048)+1e-6
    }
}

// ---------------- main: register-fused Gram->exp->dual GEMM ----------------
// CTA: 128 threads, 64 i-rows; JCH=256 (8 j-tiles of 32); grid (32, 8)
__global__ __launch_bounds__(128) void k_main() {
    __shared__ __align__(16) char XB[2][32*144];
    __shared__ __align__(16) char BCs[2][64*80];
    __shared__ __align__(16) char BYs[2][64*80];
    __shared__ float shs[JCH], sss[JCH], sqj[JCH], sqi[64];
    int tid = threadIdx.x, wid = tid >> 5, lane = tid & 31;
    int g = lane >> 2, tg = lane & 3;
    int i0 = blockIdx.x * 64;
    int split = blockIdx.y;
    int jbase = split * JCH;

    shs[tid] = g_hrn[jbase + tid];       shs[tid+128] = g_hrn[jbase + tid + 128];
    sss[tid] = g_srn[jbase + tid];       sss[tid+128] = g_srn[jbase + tid + 128];
    sqj[tid] = g_sq[jbase + tid];        sqj[tid+128] = g_sq[jbase + tid + 128];
    if (tid < 64) sqi[tid] = g_sq[i0 + tid];

    uint32_t ax[4][4];
    {
        const __nv_bfloat16* r0p = g_xbf + (i0 + wid*16 + g) * D;
        const __nv_bfloat16* r1p = r0p + 8*D;
        #pragma unroll
        for (int ks = 0; ks < 4; ks++) {
            ax[ks][0] = *(const uint32_t*)(r0p + ks*16 + 2*tg);
            ax[ks][1] = *(const uint32_t*)(r1p + ks*16 + 2*tg);
            ax[ks][2] = *(const uint32_t*)(r0p + ks*16 + 8 + 2*tg);
            ax[ks][3] = *(const uint32_t*)(r1p + ks*16 + 8 + 2*tg);
        }
    }
    #pragma unroll
    for (int q = 0; q < 2; q++) {
        int sl = tid*2 + q;
        int r = sl >> 3, c = (sl & 7) * 8;
        *(uint4*)(XB[0] + r*144 + c*2) = *(const uint4*)(g_xbf + (jbase + r) * D + c);
        int r2 = sl >> 2, j8 = (sl & 3) * 8;
        *(uint4*)(BCs[0] + r2*80 + j8*2) = *(const uint4*)(g_c1bf + r2*N + jbase + j8);
        *(uint4*)(BYs[0] + r2*80 + j8*2) = *(const uint4*)(g_ybf  + r2*N + jbase + j8);
    }
    __syncthreads();

    uint32_t uXB = (uint32_t)__cvta_generic_to_shared(XB[0]);
    uint32_t uBC = (uint32_t)__cvta_generic_to_shared(BCs[0]);
    uint32_t uBY = (uint32_t)__cvta_generic_to_shared(BYs[0]);
    float invhh = 1.0f / g_hh;
    float sqi0 = sqi[wid*16 + g], sqi1 = sqi[wid*16 + g + 8];
    float rs0 = 0.0f, rs1 = 0.0f;
    float dacc[2][8][4] = {};

    #pragma unroll 1
    for (int t = 0; t < 8; t++) {
        int buf = t & 1;
        if (t < 7) {
            #pragma unroll
            for (int q = 0; q < 2; q++) {
                int sl = tid*2 + q;
                int r = sl >> 3, c = (sl & 7) * 8;
                *(uint4*)(XB[buf^1] + r*144 + c*2) =
                    *(const uint4*)(g_xbf + (jbase + (t+1)*32 + r) * D + c);
                int r2 = sl >> 2, j8 = (sl & 3) * 8;
                *(uint4*)(BCs[buf^1] + r2*80 + j8*2) =
                    *(const uint4*)(g_c1bf + r2*N + jbase + (t+1)*32 + j8);
                *(uint4*)(BYs[buf^1] + r2*80 + j8*2) =
                    *(const uint4*)(g_ybf  + r2*N + jbase + (t+1)*32 + j8);
            }
        }
        float ga[4][4] = {};
        {
            uint32_t xb = uXB + buf*4608 + lane*144;
            #pragma unroll
            for (int ks = 0; ks < 4; ks++) {
                uint32_t b0[4], b1[4];
                ldmx4(b0, xb + (ks*16)*2);
                ldmx4(b1, xb + (ks*16 + 8)*2);
                #pragma unroll
                for (int nt = 0; nt < 4; nt++)
                    mma_bf16(ga[nt], ax[ks][0], ax[ks][1], ax[ks][2], ax[ks][3],
                             b0[nt], b1[nt]);
            }
        }
        uint32_t bc = uBC + buf*5120 + lane*80;
        uint32_t by = uBY + buf*5120 + lane*80;
        uint32_t pc0[4], pc1[4], pc2[4], pc3[4];
        uint32_t qc0[4], qc1[4], qc2[4], qc3[4];
        ldmx4(pc0, bc);            ldmx4(qc0, bc + 16);
        ldmx4(pc1, bc + 32*80);    ldmx4(qc1, bc + 32*80 + 16);
        ldmx4(pc2, by);            ldmx4(qc2, by + 16);
        ldmx4(pc3, by + 32*80);    ldmx4(qc3, by + 32*80 + 16);
        uint32_t kf[4][2], mf[4][2];
        #pragma unroll
        for (int nt = 0; nt < 4; nt++) {
            int jl = t*32 + nt*8 + 2*tg;
            float h0 = shs[jl], h1 = shs[jl+1];
            float s0 = sss[jl], s1 = sss[jl+1];
            float q0 = sqj[jl], q1 = sqj[jl+1];
            float v0 = fmaxf(sqi0 + q0 - 2.0f*ga[nt][0], 0.0f);
            float v1 = fmaxf(sqi0 + q1 - 2.0f*ga[nt][1], 0.0f);
            float v2 = fmaxf(sqi1 + q0 - 2.0f*ga[nt][2], 0.0f);
            float v3 = fmaxf(sqi1 + q1 - 2.0f*ga[nt][3], 0.0f);
            float k0 = __expf(-v0*invhh), k1 = __expf(-v1*invhh);
            float k2 = __expf(-v2*invhh), k3 = __expf(-v3*invhh);
            float m0 = k0*(sqi0*h0 + s0 - v0*h0);
            float m1 = k1*(sqi0*h1 + s1 - v1*h1);
            float m2 = k2*(sqi1*h0 + s0 - v2*h0);
            float m3 = k3*(sqi1*h1 + s1 - v3*h1);
            rs0 += k0 + k1; rs1 += k2 + k3;
            kf[nt][0] = pack_bf16(k0, k1); kf[nt][1] = pack_bf16(k2, k3);
            mf[nt][0] = pack_bf16(m0, m1); mf[nt][1] = pack_bf16(m2, m3);
        }
        {
            uint32_t ka0 = kf[0][0], ka1 = kf[0][1], ka2 = kf[1][0], ka3 = kf[1][1];
            uint32_t ma0 = mf[0][0], ma1 = mf[0][1], ma2 = mf[1][0], ma3 = mf[1][1];
            #pragma unroll
            for (int nt = 0; nt < 4; nt++) {
                mma_bf16(dacc[0][nt],   ka0, ka1, ka2, ka3, pc0[nt], qc0[nt]);
                mma_bf16(dacc[0][nt+4], ka0, ka1, ka2, ka3, pc1[nt], qc1[nt]);
                mma_bf16(dacc[1][nt],   ma0, ma1, ma2, ma3, pc2[nt], qc2[nt]);
                mma_bf16(dacc[1][nt+4], ma0, ma1, ma2, ma3, pc3[nt], qc3[nt]);
            }
        }
        {
            uint32_t ka0 = kf[2][0], ka1 = kf[2][1], ka2 = kf[3][0], ka3 = kf[3][1];
            uint32_t ma0 = mf[2][0], ma1 = mf[2][1], ma2 = mf[3][0], ma3 = mf[3][1];
            uint32_t b0[4], b1[4];
            ldmx4(b0, bc + 32);
            ldmx4(b1, bc + 48);
            #pragma unroll
            for (int nt = 0; nt < 4; nt++)
                mma_bf16(dacc[0][nt], ka0, ka1, ka2, ka3, b0[nt], b1[nt]);
            ldmx4(b0, bc + 32*80 + 32);
            ldmx4(b1, bc + 32*80 + 48);
            #pragma unroll
            for (int nt = 0; nt < 4; nt++)
                mma_bf16(dacc[0][nt+4], ka0, ka1, ka2, ka3, b0[nt], b1[nt]);
            ldmx4(b0, by + 32);
            ldmx4(b1, by + 48);
            #pragma unroll
            for (int nt = 0; nt < 4; nt++)
                mma_bf16(dacc[1][nt], ma0, ma1, ma2, ma3, b0[nt], b1[nt]);
            ldmx4(b0, by + 32*80 + 32);
            ldmx4(b1, by + 32*80 + 48);
            #pragma unroll
            for (int nt = 0; nt < 4; nt++)
                mma_bf16(dacc[1][nt+4], ma0, ma1, ma2, ma3, b0[nt], b1[nt]);
        }
        __syncthreads();
    }
    {
        int row0 = i0 + wid*16 + g;
        __nv_bfloat16* b1 = g_pacc1 + (size_t)split * N * D;
        __nv_bfloat16* b2 = g_pacc2 + (size_t)split * N * D;
        #pragma unroll
        for (int nt = 0; nt < 8; nt++) {
            int co = nt*8 + 2*tg;
            *(uint32_t*)&b1[(size_t)row0 * D + co]     = pack_bf16(dacc[0][nt][0], dacc[0][nt][1]);
            *(uint32_t*)&b1[(size_t)(row0+8) * D + co] = pack_bf16(dacc[0][nt][2], dacc[0][nt][3]);
            *(uint32_t*)&b2[(size_t)row0 * D + co]     = pack_bf16(dacc[1][nt][0], dacc[1][nt][1]);
            *(uint32_t*)&b2[(size_t)(row0+8) * D + co] = pack_bf16(dacc[1][nt][2], dacc[1][nt][3]);
        }
    }
    rs0 += __shfl_xor_sync(0xFFFFFFFFu, rs0, 1);
    rs0 += __shfl_xor_sync(0xFFFFFFFFu, rs0, 2);
    rs1 += __shfl_xor_sync(0xFFFFFFFFu, rs1, 1);
    rs1 += __shfl_xor_sync(0xFFFFFFFFu, rs1, 2);
    if (tg == 0) {
        g_prs[split * N + i0 + wid*16 + g]     = rs0;
        g_prs[split * N + i0 + wid*16 + g + 8] = rs1;
    }
}

// ---------------- finalize ----------------
__global__ void k_fin(const float* __restrict__ x, float* __restrict__ out) {
    int row  = blockIdx.x * 8 + (threadIdx.x >> 5);
    int lane = threadIdx.x & 31;
    float a10 = 0, a11 = 0, a20 = 0, a21 = 0, rstot = 0;
    #pragma unroll
    for (int s = 0; s < JSPLIT; s++) {
        const __nv_bfloat162* p1 = (const __nv_bfloat162*)(g_pacc1 + ((size_t)s * N + row) * D);
        const __nv_bfloat162* p2 = (const __nv_bfloat162*)(g_pacc2 + ((size_t)s * N + row) * D);
        float2 f1 = __bfloat1622float2(p1[lane]);
        float2 f2 = __bfloat1622float2(p2[lane]);
        a10 += f1.x; a11 += f1.y;
        a20 += f2.x; a21 += f2.y;
        rstot += g_prs[s * N + row];
    }
    float c2 = 2.0f / g_hh;
    float x0 = x[row * D + 2*lane], x1 = x[row * D + 2*lane + 1];
    float in0 = a10 + c2 * (rstot * x0 - a20);
    float in1 = a11 + c2 * (rstot * x1 - a21);
    float dot = in0 * x0 + in1 * x1;
    #pragma unroll
    for (int o = 16; o; o >>= 1) dot += __shfl_xor_sync(0xFFFFFFFFu, dot, o);
    float inv = g_isq[row];
    float g0 = in0 - x0 * (dot * inv) - x0 * (63.0f * inv);
    float g1 = in1 - x1 * (dot * inv) - x1 * (63.0f * inv);
    const float sc = 0.1f / 2048.0f;
    float d0 = fminf(fmaxf(g0 * sc, -1000.0f), 1000.0f);
    float d1 = fminf(fmaxf(g1 * sc, -1000.0f), 1000.0f);
    float2 o2 = {x0 + d0, x1 + d1};
    *(float2*)&out[row * D + 2*lane] = o2;
}

// ---------------- launch ----------------
extern "C" void kernel_launch(void* const* d_in, const int* in_sizes, int n_in,
                              void* d_out, int out_size) {
    const float* x  = (const float*)d_in[0];
    const float* mu = (const float*)d_in[1];
    float* out = (float*)d_out;

    k_combo<<<257, 256>>>(x, mu);
    k_main<<<dim3(N / 64, JSPLIT), 128>>>();
    k_fin<<<N / 8, 256>>>(x, out);
}